// round 1
// baseline (speedup 1.0000x reference)
#include <cuda_runtime.h>
#include <math.h>

#define NB 4
#define NPTS0 4096
#define STEPS 10
#define NEWP 1152
#define GDIM 256
#define HDIM 128
#define KSEL 64
#define NMAX (NPTS0 + STEPS*NEWP)   // 15616
#define NNEW (STEPS*NEWP)           // 11520

// ---------------- device state (no allocations allowed) ----------------
__device__ float g_canvas[NB*NMAX*3];
__device__ float g_h1[NB*4096*64];
__device__ float g_h2[NB*4096*128];
__device__ float g_pre[NB*128*NMAX];    // layout [b][j][i]
__device__ float g_gfeat[NB*GDIM];
__device__ float g_h[NB*HDIM];
__device__ float g_c[NB*HDIM];
__device__ float g_scores[NB*NMAX];
__device__ unsigned g_dbits[NB*NMAX];
__device__ float g_accum[4];

__device__ __forceinline__ void atomicMaxF(float* addr, float val){
    int* ai = (int*)addr;
    int old = *ai;
    while (__int_as_float(old) < val){
        int assumed = old;
        old = atomicCAS(ai, assumed, __float_as_int(val));
        if (old == assumed) break;
    }
}

// OP=0 sum, OP=1 max. All threads must participate; result broadcast to all.
template<int OP>
__device__ __forceinline__ float blockReduceT(float v){
    __shared__ float buf[32];
    #pragma unroll
    for (int o=16;o;o>>=1){
        float other = __shfl_down_sync(0xffffffffu, v, o);
        v = OP ? fmaxf(v, other) : v + other;
    }
    int w = threadIdx.x >> 5, l = threadIdx.x & 31, nw = blockDim.x >> 5;
    __syncthreads();
    if (l == 0) buf[w] = v;
    __syncthreads();
    if (w == 0){
        v = (l < nw) ? buf[l] : (OP ? -INFINITY : 0.f);
        #pragma unroll
        for (int o=16;o;o>>=1){
            float other = __shfl_down_sync(0xffffffffu, v, o);
            v = OP ? fmaxf(v, other) : v + other;
        }
        if (l == 0) buf[0] = v;
    }
    __syncthreads();
    return buf[0];
}

// ---------------- init ----------------
__global__ void k_init(const float* __restrict__ pts){
    int idx = blockIdx.x*blockDim.x + threadIdx.x;
    int total = NB*NPTS0*3;
    if (idx < total){
        int b = idx/(NPTS0*3); int r = idx%(NPTS0*3);
        g_canvas[b*NMAX*3 + r] = pts[idx];
    }
    if (idx < NB*HDIM){ g_h[idx]=0.f; g_c[idx]=0.f; }
    if (idx < NB*GDIM) g_gfeat[idx] = -INFINITY;
    if (idx < 4) g_accum[idx]=0.f;
}

// ---------------- encoder layer1 + attention "pre" cache ----------------
// grid (seg/64, NB), block 256. thread: point = t>>2, part = t&3
__global__ void k_enc1(int e0,
                       const float* __restrict__ w1, const float* __restrict__ b1,
                       const float* __restrict__ aw1){
    int b = blockIdx.y, t = threadIdx.x;
    int il = blockIdx.x*64 + (t>>2);
    int gi = e0 + il;
    int part = t & 3;
    const float* p = &g_canvas[(b*NMAX+gi)*3];
    float x = p[0], y = p[1], z = p[2];
    float h[16];
    #pragma unroll
    for (int j=0;j<16;j++){
        int c = part*16 + j;
        float v = b1[c] + x*w1[c] + y*w1[64+c] + z*w1[128+c];
        h[j] = fmaxf(v, 0.f);
    }
    float* o = &g_h1[(b*4096 + il)*64 + part*16];
    #pragma unroll
    for (int q=0;q<4;q++)
        ((float4*)o)[q] = make_float4(h[4*q],h[4*q+1],h[4*q+2],h[4*q+3]);
    #pragma unroll
    for (int j=0;j<32;j++){
        int c = part*32 + j;
        float v = x*aw1[c] + y*aw1[128+c] + z*aw1[256+c];
        g_pre[(b*128 + c)*NMAX + gi] = v;
    }
}

// ---------------- encoder layer2: h2 = relu(h1 @ W2 + b2)  (K=64, 128 cols) ----
// grid (seg/64, NB), 256 threads = 16ty x 16tx, thread tile 4pts x 8cols
__global__ void k_enc2(const float* __restrict__ w2, const float* __restrict__ b2){
    extern __shared__ float sm[];
    float* sA = sm;            // [64 k][65]
    float* sW = sm + 64*65;    // [64 k][128]
    int b = blockIdx.y, t = threadIdx.x;
    int p0 = blockIdx.x*64;
    for (int q=t; q<64*16; q+=256){
        int pt = q>>4, k4 = (q&15)<<2;
        float4 v = *(const float4*)&g_h1[(b*4096+p0+pt)*64 + k4];
        sA[(k4  )*65+pt]=v.x; sA[(k4+1)*65+pt]=v.y;
        sA[(k4+2)*65+pt]=v.z; sA[(k4+3)*65+pt]=v.w;
    }
    for (int q=t; q<2048; q+=256) ((float4*)sW)[q] = ((const float4*)w2)[q];
    __syncthreads();
    int ty = t>>4, tx = t&15;
    float acc[4][8];
    #pragma unroll
    for (int i=0;i<4;i++)
        #pragma unroll
        for (int j=0;j<8;j++) acc[i][j]=0.f;
    #pragma unroll 4
    for (int k=0;k<64;k++){
        float a0=sA[k*65+4*ty], a1=sA[k*65+4*ty+1], a2=sA[k*65+4*ty+2], a3=sA[k*65+4*ty+3];
        float4 wa = *(float4*)&sW[k*128 + 8*tx];
        float4 wb = *(float4*)&sW[k*128 + 8*tx + 4];
        float w[8] = {wa.x,wa.y,wa.z,wa.w,wb.x,wb.y,wb.z,wb.w};
        #pragma unroll
        for (int j=0;j<8;j++){
            acc[0][j] += a0*w[j]; acc[1][j] += a1*w[j];
            acc[2][j] += a2*w[j]; acc[3][j] += a3*w[j];
        }
    }
    float bb[8];
    #pragma unroll
    for (int j=0;j<8;j++) bb[j] = b2[8*tx+j];
    #pragma unroll
    for (int i=0;i<4;i++){
        int pt = p0 + 4*ty + i;
        float4 r0, r1;
        r0.x = fmaxf(acc[i][0]+bb[0],0.f); r0.y = fmaxf(acc[i][1]+bb[1],0.f);
        r0.z = fmaxf(acc[i][2]+bb[2],0.f); r0.w = fmaxf(acc[i][3]+bb[3],0.f);
        r1.x = fmaxf(acc[i][4]+bb[4],0.f); r1.y = fmaxf(acc[i][5]+bb[5],0.f);
        r1.z = fmaxf(acc[i][6]+bb[6],0.f); r1.w = fmaxf(acc[i][7]+bb[7],0.f);
        *(float4*)&g_h2[(b*4096+pt)*128 + 8*tx]     = r0;
        *(float4*)&g_h2[(b*4096+pt)*128 + 8*tx + 4] = r1;
    }
}

// ---------------- encoder layer3 + running max into gfeat ----------------
// grid (seg/128, 4 colblocks, NB), 256 threads = 16ty(8pts) x 16tx(4cols)
__global__ void k_enc3(const float* __restrict__ w3, const float* __restrict__ b3){
    extern __shared__ float sm[];
    float* sA = sm;              // [128 k][129]
    float* sW = sm + 128*129;    // [128 k][64]
    int b = blockIdx.z, cb = blockIdx.y, t = threadIdx.x;
    int p0 = blockIdx.x*128;
    for (int q=t; q<128*32; q+=256){
        int pt = q>>5, k4 = (q&31)<<2;
        float4 v = *(const float4*)&g_h2[(b*4096+p0+pt)*128 + k4];
        sA[(k4  )*129+pt]=v.x; sA[(k4+1)*129+pt]=v.y;
        sA[(k4+2)*129+pt]=v.z; sA[(k4+3)*129+pt]=v.w;
    }
    for (int q=t; q<2048; q+=256){
        int k = q>>4, c4 = (q&15)<<2;
        *(float4*)&sW[k*64 + c4] = *(const float4*)&w3[k*256 + cb*64 + c4];
    }
    __syncthreads();
    int ty = t>>4, tx = t&15;
    float acc[8][4];
    #pragma unroll
    for (int i=0;i<8;i++)
        #pragma unroll
        for (int j=0;j<4;j++) acc[i][j]=0.f;
    #pragma unroll 2
    for (int k=0;k<128;k++){
        float a[8];
        #pragma unroll
        for (int i=0;i<8;i++) a[i] = sA[k*129 + 8*ty + i];
        float4 w = *(float4*)&sW[k*64 + 4*tx];
        #pragma unroll
        for (int i=0;i<8;i++){
            acc[i][0] += a[i]*w.x; acc[i][1] += a[i]*w.y;
            acc[i][2] += a[i]*w.z; acc[i][3] += a[i]*w.w;
        }
    }
    float m[4];
    #pragma unroll
    for (int j=0;j<4;j++){
        float mv = acc[0][j];
        #pragma unroll
        for (int i=1;i<8;i++) mv = fmaxf(mv, acc[i][j]);
        m[j] = mv + b3[cb*64 + 4*tx + j];
    }
    __syncthreads();
    float* red = sA;   // reuse, need 16*64 floats
    #pragma unroll
    for (int j=0;j<4;j++) red[ty*64 + 4*tx + j] = m[j];
    __syncthreads();
    if (t < 64){
        float v = red[t];
        #pragma unroll
        for (int r=1;r<16;r++) v = fmaxf(v, red[r*64 + t]);
        atomicMaxF(&g_gfeat[b*GDIM + cb*64 + t], v);
    }
}

// ---------------- attention scores (factorized) ----------------
// grid (N/128, NB), 128 threads
__global__ void k_att(int N,
                      const float* __restrict__ aw1, const float* __restrict__ ab1,
                      const float* __restrict__ aw2, const float* __restrict__ ab2){
    __shared__ float base[128], w2s[128];
    int b = blockIdx.y, t = threadIdx.x;
    {
        float s = ab1[t];
        const float* gf = &g_gfeat[b*GDIM];
        #pragma unroll 4
        for (int k=0;k<GDIM;k++) s += gf[k]*aw1[(3+k)*128 + t];
        const float* hh = &g_h[b*HDIM];
        #pragma unroll 4
        for (int k=0;k<HDIM;k++) s += hh[k]*aw1[(3+GDIM+k)*128 + t];
        base[t] = s; w2s[t] = aw2[t];
    }
    __syncthreads();
    int i = blockIdx.x*128 + t;
    float acc = ab2[0];
    const float* pr = &g_pre[(b*128)*NMAX + i];
    #pragma unroll 8
    for (int j=0;j<128;j++)
        acc += fmaxf(pr[j*NMAX] + base[j], 0.f) * w2s[j];
    g_scores[b*NMAX + i] = acc;
}

// ---------------- fused per-batch tail ----------------
// softmax+center -> dists -> radix-select top-64 -> patch_feat -> LSTM -> refine -> scatter
// grid NB, 1024 threads
__global__ void k_tail(int N,
    const float* __restrict__ wih, const float* __restrict__ whh,
    const float* __restrict__ bih, const float* __restrict__ bhh,
    const float* __restrict__ rw1, const float* __restrict__ rb1,
    const float* __restrict__ rw2, const float* __restrict__ rb2){
    __shared__ unsigned s_hist[256];
    __shared__ int s_ibc[4];
    __shared__ float s_in[262];
    __shared__ float s_gates[512];
    __shared__ float s_h[128];
    __shared__ float s_hold[128];
    __shared__ float s_r[128];
    int b = blockIdx.x, t = threadIdx.x;
    const float* sc = &g_scores[b*NMAX];
    const float* cv = &g_canvas[b*NMAX*3];

    // A: softmax max
    float mx = -INFINITY;
    for (int i=t;i<N;i+=1024) mx = fmaxf(mx, sc[i]);
    mx = blockReduceT<1>(mx);
    // B: exp-sum + weighted center
    float es=0.f, cx=0.f, cy=0.f, cz=0.f;
    for (int i=t;i<N;i+=1024){
        float e = expf(sc[i]-mx);
        es += e; cx += e*cv[3*i]; cy += e*cv[3*i+1]; cz += e*cv[3*i+2];
    }
    es = blockReduceT<0>(es);
    cx = blockReduceT<0>(cx); cy = blockReduceT<0>(cy); cz = blockReduceT<0>(cz);
    float ctr0 = cx/es, ctr1 = cy/es, ctr2 = cz/es;
    // C: squared dists as uint bits (nonneg floats order-preserving)
    for (int i=t;i<N;i+=1024){
        float dx=cv[3*i]-ctr0, dy=cv[3*i+1]-ctr1, dz=cv[3*i+2]-ctr2;
        g_dbits[b*NMAX+i] = __float_as_uint(dx*dx+dy*dy+dz*dz);
    }
    __syncthreads();
    // D: radix select K-th smallest
    unsigned prefix = 0; int krem = KSEL;
    for (int rd=0; rd<4; rd++){
        int shift = 24 - 8*rd;
        unsigned maskhi = (rd==0) ? 0u : (0xFFFFFFFFu << (shift+8));
        if (t < 256) s_hist[t] = 0u;
        __syncthreads();
        for (int i=t;i<N;i+=1024){
            unsigned u = g_dbits[b*NMAX+i];
            if ((u & maskhi) == prefix) atomicAdd(&s_hist[(u>>shift)&255], 1u);
        }
        __syncthreads();
        if (t == 0){
            unsigned cum = 0; int sel = 255;
            for (int bin=0;bin<256;bin++){
                unsigned c = s_hist[bin];
                if (cum + c >= (unsigned)krem){ sel = bin; break; }
                cum += c;
            }
            s_ibc[0] = sel; s_ibc[1] = krem - (int)cum;
        }
        __syncthreads();
        prefix |= ((unsigned)s_ibc[0]) << shift;
        krem = s_ibc[1];
        __syncthreads();
    }
    // E: sum coordinates of the 64 nearest (ties by arrival order)
    if (t == 0) s_ibc[2] = 0;
    __syncthreads();
    float sx=0.f, sy=0.f, sz=0.f;
    for (int i=t;i<N;i+=1024){
        unsigned u = g_dbits[b*NMAX+i];
        bool take = false;
        if (u < prefix) take = true;
        else if (u == prefix){
            int pos = atomicAdd(&s_ibc[2], 1);
            if (pos < krem) take = true;
        }
        if (take){ sx += cv[3*i]; sy += cv[3*i+1]; sz += cv[3*i+2]; }
    }
    sx = blockReduceT<0>(sx); sy = blockReduceT<0>(sy); sz = blockReduceT<0>(sz);
    float pf0 = sx/(float)KSEL - ctr0;
    float pf1 = sy/(float)KSEL - ctr1;
    float pf2 = sz/(float)KSEL - ctr2;
    // F: LSTM
    if (t < GDIM) s_in[t] = g_gfeat[b*GDIM + t];
    if (t >= GDIM && t < GDIM+3) s_in[t] = (t==256)?ctr0:((t==257)?ctr1:ctr2);
    if (t >= 259 && t < 262) s_in[t] = (t==259)?pf0:((t==260)?pf1:pf2);
    if (t < HDIM) s_hold[t] = g_h[b*HDIM + t];
    __syncthreads();
    if (t < 512){
        float g = bih[t] + bhh[t];
        #pragma unroll 2
        for (int k=0;k<262;k++) g += s_in[k]*wih[k*512 + t];
        #pragma unroll 2
        for (int k=0;k<128;k++) g += s_hold[k]*whh[k*512 + t];
        s_gates[t] = g;
    }
    __syncthreads();
    if (t < 128){
        float gi = s_gates[t], gf = s_gates[128+t], gg = s_gates[256+t], go = s_gates[384+t];
        float si = 1.f/(1.f+expf(-gi));
        float sf = 1.f/(1.f+expf(-gf));
        float so = 1.f/(1.f+expf(-go));
        float cn = sf*g_c[b*HDIM+t] + si*tanhf(gg);
        float hn = so*tanhf(cn);
        g_c[b*HDIM+t] = cn; g_h[b*HDIM+t] = hn; s_h[t] = hn;
    }
    __syncthreads();
    // G: refine hidden
    if (t < 128){
        float v = rb1[t];
        #pragma unroll 2
        for (int k=0;k<128;k++) v += s_h[k]*rw1[k*128 + t];
        s_r[t] = fmaxf(v, 0.f);
    }
    __syncthreads();
    // H: new points, scatter into canvas
    for (int j=t; j<NEWP*3; j+=1024){
        float v = rb2[j];
        #pragma unroll 4
        for (int k=0;k<128;k++) v += s_r[k]*rw2[k*(NEWP*3) + j];
        int d = j % 3, pt = j / 3;
        float ctr = (d==0)?ctr0:((d==1)?ctr1:ctr2);
        g_canvas[(b*NMAX + N + pt)*3 + d] = v*0.02f + ctr;
    }
}

// ---------------- chamfer: directional min-sums ----------------
// mode 0: X=canvas[:4096] Y=gt ; 1: X=gt Y=canvas[:4096]
// mode 2: X=canvas[4096:] Y=gt ; 3: X=gt Y=canvas[4096:]
__global__ void k_cham(const float* __restrict__ gt, int mode){
    __shared__ float sy[256*3];
    int b = blockIdx.y, t = threadIdx.x;
    const float* cin = &g_canvas[b*NMAX*3];
    const float* gb  = &gt[b*NPTS0*3];
    const float *X, *Y; int nx, ny;
    if (mode == 0){ X=cin;          Y=gb;          nx=NPTS0; ny=NPTS0; }
    else if (mode == 1){ X=gb;      Y=cin;         nx=NPTS0; ny=NPTS0; }
    else if (mode == 2){ X=cin+NPTS0*3; Y=gb;      nx=NNEW;  ny=NPTS0; }
    else { X=gb;          Y=cin+NPTS0*3;           nx=NPTS0; ny=NNEW;  }
    int base = blockIdx.x*1024;
    float xs[4][3]; float m[4]; bool val[4];
    #pragma unroll
    for (int i=0;i<4;i++){
        int xi = base + i*256 + t;
        val[i] = xi < nx;
        int cl = val[i] ? xi : 0;
        xs[i][0]=X[cl*3]; xs[i][1]=X[cl*3+1]; xs[i][2]=X[cl*3+2];
        m[i] = INFINITY;
    }
    for (int y0=0; y0<ny; y0+=256){
        __syncthreads();
        for (int q=t; q<768; q+=256) sy[q] = Y[y0*3 + q];
        __syncthreads();
        #pragma unroll 4
        for (int j=0;j<256;j++){
            float yx=sy[3*j], yy=sy[3*j+1], yz=sy[3*j+2];
            #pragma unroll
            for (int i=0;i<4;i++){
                float dx=xs[i][0]-yx, dy=xs[i][1]-yy, dz=xs[i][2]-yz;
                m[i] = fminf(m[i], dx*dx + dy*dy + dz*dz);
            }
        }
    }
    float ssum = 0.f;
    #pragma unroll
    for (int i=0;i<4;i++) if (val[i]) ssum += m[i];
    ssum = blockReduceT<0>(ssum);
    if (t == 0) atomicAdd(&g_accum[mode], ssum);
}

__global__ void k_final(float* out){
    if (threadIdx.x == 0){
        float a0 = g_accum[0] / (float)(NB*NPTS0);
        float a1 = g_accum[1] / (float)(NB*NPTS0);
        float a2 = g_accum[2] / (float)(NB*NNEW);
        float a3 = g_accum[3] / (float)(NB*NPTS0);
        out[0] = 0.1f*(a0 + a1) + 1.0f*(a2 + a3);
    }
}

// ---------------- host ----------------
extern "C" void kernel_launch(void* const* d_in, const int* in_sizes, int n_in,
                              void* d_out, int out_size){
    const float* points   = (const float*)d_in[0];
    const float* gt       = (const float*)d_in[1];
    const float* enc_w1   = (const float*)d_in[2];
    const float* enc_b1   = (const float*)d_in[3];
    const float* enc_w2   = (const float*)d_in[4];
    const float* enc_b2   = (const float*)d_in[5];
    const float* enc_w3   = (const float*)d_in[6];
    const float* enc_b3   = (const float*)d_in[7];
    const float* att_w1   = (const float*)d_in[8];
    const float* att_b1   = (const float*)d_in[9];
    const float* att_w2   = (const float*)d_in[10];
    const float* att_b2   = (const float*)d_in[11];
    const float* lstm_wih = (const float*)d_in[12];
    const float* lstm_whh = (const float*)d_in[13];
    const float* lstm_bih = (const float*)d_in[14];
    const float* lstm_bhh = (const float*)d_in[15];
    const float* ref_w1   = (const float*)d_in[16];
    const float* ref_b1   = (const float*)d_in[17];
    const float* ref_w2   = (const float*)d_in[18];
    const float* ref_b2   = (const float*)d_in[19];

    const int SM2 = (64*65 + 64*128)*4;     // 49408
    const int SM3 = (128*129 + 128*64)*4;   // 98816
    cudaFuncSetAttribute(k_enc2, cudaFuncAttributeMaxDynamicSharedMemorySize, SM2);
    cudaFuncSetAttribute(k_enc3, cudaFuncAttributeMaxDynamicSharedMemorySize, SM3);

    k_init<<<48,1024>>>(points);

    int encoded = 0;
    for (int s=0; s<STEPS; s++){
        int N   = NPTS0 + NEWP*s;
        int seg = N - encoded;
        int e0  = encoded;
        dim3 g1(seg/64, NB);        k_enc1<<<g1,256>>>(e0, enc_w1, enc_b1, att_w1);
        dim3 g2(seg/64, NB);        k_enc2<<<g2,256,SM2>>>(enc_w2, enc_b2);
        dim3 g3(seg/128, 4, NB);    k_enc3<<<g3,256,SM3>>>(enc_w3, enc_b3);
        encoded = N;
        dim3 ga(N/128, NB);         k_att<<<ga,128>>>(N, att_w1, att_b1, att_w2, att_b2);
        k_tail<<<NB,1024>>>(N, lstm_wih, lstm_whh, lstm_bih, lstm_bhh,
                            ref_w1, ref_b1, ref_w2, ref_b2);
    }
    k_cham<<<dim3(4,NB),256>>>(gt, 0);
    k_cham<<<dim3(4,NB),256>>>(gt, 1);
    k_cham<<<dim3(12,NB),256>>>(gt, 2);
    k_cham<<<dim3(4,NB),256>>>(gt, 3);
    k_final<<<1,32>>>((float*)d_out);
}

// round 4
// speedup vs baseline: 1.6966x; 1.6966x over previous
#include <cuda_runtime.h>
#include <math.h>

#define NB 4
#define NPTS0 4096
#define STEPS 10
#define NEWP 1152
#define GDIM 256
#define HDIM 128
#define KSEL 64
#define NMAX (NPTS0 + STEPS*NEWP)   // 15616
#define NNEW (STEPS*NEWP)           // 11520

typedef unsigned long long ull;

// ---------------- device state (no allocations allowed) ----------------
__device__ float g_canvas[NB*NMAX*3];
__device__ float g_h1[NB*4096*64];
__device__ float g_h2[NB*4096*128];
__device__ float g_pre[NB*128*NMAX];    // layout [b][j][i]
__device__ float g_gfeat[NB*GDIM];
__device__ float g_h[NB*HDIM];
__device__ float g_c[NB*HDIM];
__device__ float g_ctr[NB*3];
__device__ float g_scores[NB*NMAX];
__device__ unsigned g_dbits[NB*NMAX];
__device__ unsigned g_xmin[4*NB*16384];
__device__ float g_accum[4];

// ---------------- packed f32x2 helpers (FFMA2 path) ----------------
__device__ __forceinline__ ull pk(float lo, float hi){
    ull r; asm("mov.b64 %0,{%1,%2};" : "=l"(r) : "f"(lo), "f"(hi)); return r;
}
__device__ __forceinline__ void upk(ull v, float& lo, float& hi){
    asm("mov.b64 {%0,%1},%2;" : "=f"(lo), "=f"(hi) : "l"(v));
}
__device__ __forceinline__ ull fma2(ull a, ull b, ull c){
    ull d; asm("fma.rn.f32x2 %0,%1,%2,%3;" : "=l"(d) : "l"(a), "l"(b), "l"(c)); return d;
}
__device__ __forceinline__ ull mul2(ull a, ull b){
    ull d; asm("mul.rn.f32x2 %0,%1,%2;" : "=l"(d) : "l"(a), "l"(b)); return d;
}

__device__ __forceinline__ void atomicMaxF(float* addr, float val){
    int* ai = (int*)addr;
    int old = *ai;
    while (__int_as_float(old) < val){
        int assumed = old;
        old = atomicCAS(ai, assumed, __float_as_int(val));
        if (old == assumed) break;
    }
}

// float <-> order-preserving sortable uint
__device__ __forceinline__ unsigned f2s(float f){
    unsigned u = __float_as_uint(f);
    return u ^ ((unsigned)(((int)u) >> 31) | 0x80000000u);
}
__device__ __forceinline__ float s2f(unsigned s){
    unsigned u = (s & 0x80000000u) ? (s ^ 0x80000000u) : ~s;
    return __uint_as_float(u);
}

// OP=0 sum, OP=1 max. All threads participate; result broadcast.
template<int OP>
__device__ __forceinline__ float blockReduceT(float v){
    __shared__ float buf[32];
    #pragma unroll
    for (int o=16;o;o>>=1){
        float other = __shfl_down_sync(0xffffffffu, v, o);
        v = OP ? fmaxf(v, other) : v + other;
    }
    int w = threadIdx.x >> 5, l = threadIdx.x & 31, nw = blockDim.x >> 5;
    __syncthreads();
    if (l == 0) buf[w] = v;
    __syncthreads();
    if (w == 0){
        v = (l < nw) ? buf[l] : (OP ? -INFINITY : 0.f);
        #pragma unroll
        for (int o=16;o;o>>=1){
            float other = __shfl_down_sync(0xffffffffu, v, o);
            v = OP ? fmaxf(v, other) : v + other;
        }
        if (l == 0) buf[0] = v;
    }
    __syncthreads();
    return buf[0];
}

// ---------------- init ----------------
__global__ void k_init(const float* __restrict__ pts){
    int idx = blockIdx.x*blockDim.x + threadIdx.x;
    int total = NB*NPTS0*3;
    if (idx < total){
        int b = idx/(NPTS0*3); int r = idx%(NPTS0*3);
        g_canvas[b*NMAX*3 + r] = pts[idx];
    }
    if (idx < NB*HDIM){ g_h[idx]=0.f; g_c[idx]=0.f; }
    if (idx < NB*GDIM) g_gfeat[idx] = -INFINITY;
    if (idx < 4) g_accum[idx]=0.f;
    if (idx < 4*NB*16384) g_xmin[idx] = 0xFFFFFFFFu;
}

// ---------------- encoder layer1 + attention "pre" cache ----------------
__global__ void k_enc1(int e0,
                       const float* __restrict__ w1, const float* __restrict__ b1,
                       const float* __restrict__ aw1){
    int b = blockIdx.y, t = threadIdx.x;
    int il = blockIdx.x*64 + (t>>2);
    int gi = e0 + il;
    int part = t & 3;
    const float* p = &g_canvas[(b*NMAX+gi)*3];
    float x = p[0], y = p[1], z = p[2];
    float h[16];
    #pragma unroll
    for (int j=0;j<16;j++){
        int c = part*16 + j;
        float v = b1[c] + x*w1[c] + y*w1[64+c] + z*w1[128+c];
        h[j] = fmaxf(v, 0.f);
    }
    float* o = &g_h1[(b*4096 + il)*64 + part*16];
    #pragma unroll
    for (int q=0;q<4;q++)
        ((float4*)o)[q] = make_float4(h[4*q],h[4*q+1],h[4*q+2],h[4*q+3]);
    #pragma unroll
    for (int j=0;j<32;j++){
        int c = part*32 + j;
        float v = x*aw1[c] + y*aw1[128+c] + z*aw1[256+c];
        g_pre[(b*128 + c)*NMAX + gi] = v;
    }
}

// ---------------- encoder layer2 (packed FFMA2) ----------------
// grid (seg/64, NB), 256 threads = 16ty x 16tx, tile 4pts x 8cols (4 col-pairs)
__global__ void k_enc2(const float* __restrict__ w2, const float* __restrict__ b2){
    extern __shared__ float sm[];
    float* sA = sm;            // [64 k][65]
    float* sW = sm + 64*65;    // [64 k][128]  (byte offset 16640, 8B-aligned)
    int b = blockIdx.y, t = threadIdx.x;
    int p0 = blockIdx.x*64;
    for (int q=t; q<64*16; q+=256){
        int pt = q>>4, k4 = (q&15)<<2;
        float4 v = *(const float4*)&g_h1[(b*4096+p0+pt)*64 + k4];
        sA[(k4  )*65+pt]=v.x; sA[(k4+1)*65+pt]=v.y;
        sA[(k4+2)*65+pt]=v.z; sA[(k4+3)*65+pt]=v.w;
    }
    for (int q=t; q<2048; q+=256) ((float4*)sW)[q] = ((const float4*)w2)[q];
    __syncthreads();
    int ty = t>>4, tx = t&15;
    ull acc[4][4];
    #pragma unroll
    for (int i=0;i<4;i++)
        #pragma unroll
        for (int j=0;j<4;j++) acc[i][j]=0ull;
    #pragma unroll 2
    for (int k=0;k<64;k++){
        ull ad[4];
        #pragma unroll
        for (int i=0;i<4;i++){ float a = sA[k*65+4*ty+i]; ad[i] = pk(a,a); }
        ull wp[4];
        #pragma unroll
        for (int j=0;j<4;j++) wp[j] = *(ull*)&sW[k*128 + 8*tx + 2*j];
        #pragma unroll
        for (int i=0;i<4;i++)
            #pragma unroll
            for (int j=0;j<4;j++) acc[i][j] = fma2(ad[i], wp[j], acc[i][j]);
    }
    float bb[8];
    #pragma unroll
    for (int j=0;j<8;j++) bb[j] = b2[8*tx+j];
    #pragma unroll
    for (int i=0;i<4;i++){
        int pt = p0 + 4*ty + i;
        float r[8];
        #pragma unroll
        for (int j=0;j<4;j++){
            float lo,hi; upk(acc[i][j], lo, hi);
            r[2*j]   = fmaxf(lo + bb[2*j],   0.f);
            r[2*j+1] = fmaxf(hi + bb[2*j+1], 0.f);
        }
        *(float4*)&g_h2[(b*4096+pt)*128 + 8*tx]     = make_float4(r[0],r[1],r[2],r[3]);
        *(float4*)&g_h2[(b*4096+pt)*128 + 8*tx + 4] = make_float4(r[4],r[5],r[6],r[7]);
    }
}

// ---------------- encoder layer3 + running max (packed FFMA2) ----------------
// grid (seg/128, 4 colblocks, NB), 256 threads = 16ty(8pts=4 pt-pairs) x 16tx(4cols)
__global__ void k_enc3(const float* __restrict__ w3, const float* __restrict__ b3){
    extern __shared__ float sm[];
    float* sA = sm;              // [128 k][130]  (even stride -> aligned ull reads)
    float* sW = sm + 128*130;    // [128 k][64]
    int b = blockIdx.z, cb = blockIdx.y, t = threadIdx.x;
    int p0 = blockIdx.x*128;
    for (int q=t; q<128*32; q+=256){
        int pt = q>>5, k4 = (q&31)<<2;
        float4 v = *(const float4*)&g_h2[(b*4096+p0+pt)*128 + k4];
        sA[(k4  )*130+pt]=v.x; sA[(k4+1)*130+pt]=v.y;
        sA[(k4+2)*130+pt]=v.z; sA[(k4+3)*130+pt]=v.w;
    }
    for (int q=t; q<2048; q+=256){
        int k = q>>4, c4 = (q&15)<<2;
        *(float4*)&sW[k*64 + c4] = *(const float4*)&w3[k*256 + cb*64 + c4];
    }
    __syncthreads();
    int ty = t>>4, tx = t&15;
    ull acc[4][4];   // [pt-pair][col]
    #pragma unroll
    for (int i=0;i<4;i++)
        #pragma unroll
        for (int j=0;j<4;j++) acc[i][j]=0ull;
    #pragma unroll 2
    for (int k=0;k<128;k++){
        ull ap[4];
        #pragma unroll
        for (int i=0;i<4;i++) ap[i] = *(ull*)&sA[k*130 + 8*ty + 2*i];
        float4 w = *(float4*)&sW[k*64 + 4*tx];
        ull wd[4] = { pk(w.x,w.x), pk(w.y,w.y), pk(w.z,w.z), pk(w.w,w.w) };
        #pragma unroll
        for (int i=0;i<4;i++)
            #pragma unroll
            for (int j=0;j<4;j++) acc[i][j] = fma2(ap[i], wd[j], acc[i][j]);
    }
    float m[4];
    #pragma unroll
    for (int j=0;j<4;j++){
        float best = -INFINITY;
        #pragma unroll
        for (int i=0;i<4;i++){
            float lo,hi; upk(acc[i][j], lo, hi);
            best = fmaxf(best, fmaxf(lo,hi));
        }
        m[j] = best + b3[cb*64 + 4*tx + j];
    }
    __syncthreads();
    float* red = sA;   // reuse
    #pragma unroll
    for (int j=0;j<4;j++) red[ty*64 + 4*tx + j] = m[j];
    __syncthreads();
    if (t < 64){
        float v = red[t];
        #pragma unroll
        for (int r=1;r<16;r++) v = fmaxf(v, red[r*64 + t]);
        atomicMaxF(&g_gfeat[b*GDIM + cb*64 + t], v);
    }
}

// ---------------- attention scores (factorized) ----------------
__global__ void k_att(int N,
                      const float* __restrict__ aw1, const float* __restrict__ ab1,
                      const float* __restrict__ aw2, const float* __restrict__ ab2){
    __shared__ float base[128], w2s[128];
    int b = blockIdx.y, t = threadIdx.x;
    {
        float s = ab1[t];
        const float* gf = &g_gfeat[b*GDIM];
        #pragma unroll 4
        for (int k=0;k<GDIM;k++) s += gf[k]*aw1[(3+k)*128 + t];
        const float* hh = &g_h[b*HDIM];
        #pragma unroll 4
        for (int k=0;k<HDIM;k++) s += hh[k]*aw1[(3+GDIM+k)*128 + t];
        base[t] = s; w2s[t] = aw2[t];
    }
    __syncthreads();
    int i = blockIdx.x*128 + t;
    const float* pr = &g_pre[(b*128)*NMAX + i];
    float a0=0.f, a1=0.f, a2=0.f, a3=0.f;
    #pragma unroll 4
    for (int j=0;j<128;j+=4){
        a0 += fmaxf(pr[(j  )*NMAX] + base[j  ], 0.f) * w2s[j  ];
        a1 += fmaxf(pr[(j+1)*NMAX] + base[j+1], 0.f) * w2s[j+1];
        a2 += fmaxf(pr[(j+2)*NMAX] + base[j+2], 0.f) * w2s[j+2];
        a3 += fmaxf(pr[(j+3)*NMAX] + base[j+3], 0.f) * w2s[j+3];
    }
    g_scores[b*NMAX + i] = ab2[0] + ((a0+a1)+(a2+a3));
}

// ---------------- fused per-batch tail (no refine GEMM) ----------------
__global__ void k_tail(int N,
    const float* __restrict__ wih, const float* __restrict__ whh,
    const float* __restrict__ bih, const float* __restrict__ bhh){
    __shared__ unsigned s_hist[256];
    __shared__ int s_ibc[4];
    __shared__ float s_in[262];
    __shared__ float s_gates[512];
    __shared__ float s_hold[128];
    int b = blockIdx.x, t = threadIdx.x;
    const float* sc = &g_scores[b*NMAX];
    const float* cv = &g_canvas[b*NMAX*3];

    float mx = -INFINITY;
    for (int i=t;i<N;i+=1024) mx = fmaxf(mx, sc[i]);
    mx = blockReduceT<1>(mx);
    float es=0.f, cx=0.f, cy=0.f, cz=0.f;
    for (int i=t;i<N;i+=1024){
        float e = expf(sc[i]-mx);
        es += e; cx += e*cv[3*i]; cy += e*cv[3*i+1]; cz += e*cv[3*i+2];
    }
    es = blockReduceT<0>(es);
    cx = blockReduceT<0>(cx); cy = blockReduceT<0>(cy); cz = blockReduceT<0>(cz);
    float ctr0 = cx/es, ctr1 = cy/es, ctr2 = cz/es;
    if (t < 3) g_ctr[b*3+t] = (t==0)?ctr0:((t==1)?ctr1:ctr2);
    for (int i=t;i<N;i+=1024){
        float dx=cv[3*i]-ctr0, dy=cv[3*i+1]-ctr1, dz=cv[3*i+2]-ctr2;
        g_dbits[b*NMAX+i] = __float_as_uint(dx*dx+dy*dy+dz*dz);
    }
    __syncthreads();
    unsigned prefix = 0; int krem = KSEL;
    for (int rd=0; rd<4; rd++){
        int shift = 24 - 8*rd;
        unsigned maskhi = (rd==0) ? 0u : (0xFFFFFFFFu << (shift+8));
        if (t < 256) s_hist[t] = 0u;
        __syncthreads();
        for (int i=t;i<N;i+=1024){
            unsigned u = g_dbits[b*NMAX+i];
            if ((u & maskhi) == prefix) atomicAdd(&s_hist[(u>>shift)&255], 1u);
        }
        __syncthreads();
        if (t == 0){
            unsigned cum = 0; int sel = 255;
            for (int bin=0;bin<256;bin++){
                unsigned c = s_hist[bin];
                if (cum + c >= (unsigned)krem){ sel = bin; break; }
                cum += c;
            }
            s_ibc[0] = sel; s_ibc[1] = krem - (int)cum;
        }
        __syncthreads();
        prefix |= ((unsigned)s_ibc[0]) << shift;
        krem = s_ibc[1];
        __syncthreads();
    }
    if (t == 0) s_ibc[2] = 0;
    __syncthreads();
    float sx=0.f, sy=0.f, sz=0.f;
    for (int i=t;i<N;i+=1024){
        unsigned u = g_dbits[b*NMAX+i];
        bool take = false;
        if (u < prefix) take = true;
        else if (u == prefix){
            int pos = atomicAdd(&s_ibc[2], 1);
            if (pos < krem) take = true;
        }
        if (take){ sx += cv[3*i]; sy += cv[3*i+1]; sz += cv[3*i+2]; }
    }
    sx = blockReduceT<0>(sx); sy = blockReduceT<0>(sy); sz = blockReduceT<0>(sz);
    float pf0 = sx/(float)KSEL - ctr0;
    float pf1 = sy/(float)KSEL - ctr1;
    float pf2 = sz/(float)KSEL - ctr2;
    if (t < GDIM) s_in[t] = g_gfeat[b*GDIM + t];
    if (t >= GDIM && t < GDIM+3) s_in[t] = (t==256)?ctr0:((t==257)?ctr1:ctr2);
    if (t >= 259 && t < 262) s_in[t] = (t==259)?pf0:((t==260)?pf1:pf2);
    if (t < HDIM) s_hold[t] = g_h[b*HDIM + t];
    __syncthreads();
    if (t < 512){
        float g = bih[t] + bhh[t];
        #pragma unroll 2
        for (int k=0;k<262;k++) g += s_in[k]*wih[k*512 + t];
        #pragma unroll 2
        for (int k=0;k<128;k++) g += s_hold[k]*whh[k*512 + t];
        s_gates[t] = g;
    }
    __syncthreads();
    if (t < 128){
        float gi = s_gates[t], gf = s_gates[128+t], gg = s_gates[256+t], go = s_gates[384+t];
        float si = 1.f/(1.f+expf(-gi));
        float sf = 1.f/(1.f+expf(-gf));
        float so = 1.f/(1.f+expf(-go));
        float cn = sf*g_c[b*HDIM+t] + si*tanhf(gg);
        float hn = so*tanhf(cn);
        g_c[b*HDIM+t] = cn; g_h[b*HDIM+t] = hn;
    }
}

// ---------------- refine: new points GEMM, full-chip ----------------
// grid (27, NB), 128 threads; each block -> 128 output scalars
__global__ void k_refine(int N,
    const float* __restrict__ rw1, const float* __restrict__ rb1,
    const float* __restrict__ rw2, const float* __restrict__ rb2){
    __shared__ float s_h[128], s_r[128];
    int b = blockIdx.y, t = threadIdx.x;
    s_h[t] = g_h[b*HDIM + t];
    __syncthreads();
    {
        float v = rb1[t];
        #pragma unroll 4
        for (int k=0;k<128;k++) v += s_h[k]*rw1[k*128 + t];
        s_r[t] = fmaxf(v, 0.f);
    }
    __syncthreads();
    int j = blockIdx.x*128 + t;
    float v = rb2[j];
    #pragma unroll 4
    for (int k=0;k<128;k++) v += s_r[k]*rw2[k*(NEWP*3) + j];
    int d = j % 3, pt = j / 3;
    g_canvas[(b*NMAX + N + pt)*3 + d] = v*0.02f + g_ctr[b*3 + d];
}

// ---------------- chamfer: packed-FFMA2 pairwise min (full chip) ----------------
// min_y d2 = |x|^2 + min_y(|y|^2 - 2 x.y). Partial mins per y-tile -> atomicMin.
// grid (23, 6, 16): z = mode*4 + b; block 128 threads, 4 x per thread (512 x/block),
// y-tile 2048, staged in 128-y chunks with |y|^2 precomputed.
__global__ void k_cham2(const float* __restrict__ gt){
    __shared__ __align__(16) float s_yx[128];
    __shared__ __align__(16) float s_yy[128];
    __shared__ __align__(16) float s_yz[128];
    __shared__ __align__(16) float s_n[128];
    int z = blockIdx.z; int mode = z >> 2; int b = z & 3;
    const float* cin = &g_canvas[b*NMAX*3];
    const float* gb  = &gt[b*NPTS0*3];
    const float *X, *Y; int nx, ny;
    if (mode == 0){ X=cin;          Y=gb;          nx=NPTS0; ny=NPTS0; }
    else if (mode == 1){ X=gb;      Y=cin;         nx=NPTS0; ny=NPTS0; }
    else if (mode == 2){ X=cin+NPTS0*3; Y=gb;      nx=NNEW;  ny=NPTS0; }
    else { X=gb;          Y=cin+NPTS0*3;           nx=NPTS0; ny=NNEW;  }
    int x0 = blockIdx.x*512;
    int y0 = blockIdx.y*2048;
    if (x0 >= nx || y0 >= ny) return;
    int yend = min(y0 + 2048, ny);
    int t = threadIdx.x;

    ull xd[4][3]; bool val[4]; float me[4], mo[4];
    #pragma unroll
    for (int i=0;i<4;i++){
        int xi = x0 + i*128 + t;
        val[i] = xi < nx;
        int cl = val[i] ? xi : 0;
        float a=X[cl*3], bb=X[cl*3+1], c=X[cl*3+2];
        xd[i][0]=pk(a,a); xd[i][1]=pk(bb,bb); xd[i][2]=pk(c,c);
        me[i]=INFINITY; mo[i]=INFINITY;
    }
    ull c_m2 = pk(-2.f,-2.f);

    for (int yb=y0; yb<yend; yb+=128){
        __syncthreads();
        {
            int yi = yb + t;
            float a=Y[yi*3], bb=Y[yi*3+1], c=Y[yi*3+2];
            s_yx[t]=a; s_yy[t]=bb; s_yz[t]=c;
            s_n[t]=a*a + bb*bb + c*c;
        }
        __syncthreads();
        #pragma unroll 4
        for (int j=0;j<64;j++){
            ull yx = ((ull*)s_yx)[j];
            ull yy = ((ull*)s_yy)[j];
            ull yz = ((ull*)s_yz)[j];
            ull nn = ((ull*)s_n)[j];
            #pragma unroll
            for (int i=0;i<4;i++){
                ull dot = fma2(xd[i][2], yz, fma2(xd[i][1], yy, mul2(xd[i][0], yx)));
                ull d   = fma2(dot, c_m2, nn);
                float lo,hi; upk(d, lo, hi);
                me[i] = fminf(me[i], lo);
                mo[i] = fminf(mo[i], hi);
            }
        }
    }
    #pragma unroll
    for (int i=0;i<4;i++){
        if (val[i]){
            float m = fminf(me[i], mo[i]);
            atomicMin(&g_xmin[(mode*NB + b)*16384 + x0 + i*128 + t], f2s(m));
        }
    }
}

// sum pass: accum[mode] = sum_x (|x|^2 + min-part)
__global__ void k_chamsum(const float* __restrict__ gt){
    int mode = blockIdx.z, b = blockIdx.y, t = threadIdx.x;
    const float* cin = &g_canvas[b*NMAX*3];
    const float* gb  = &gt[b*NPTS0*3];
    const float* X; int nx;
    if (mode == 0){ X=cin; nx=NPTS0; }
    else if (mode == 1){ X=gb; nx=NPTS0; }
    else if (mode == 2){ X=cin+NPTS0*3; nx=NNEW; }
    else { X=gb; nx=NPTS0; }
    int xi = blockIdx.x*256 + t;
    float v = 0.f;
    if (xi < nx){
        float f = s2f(g_xmin[(mode*NB + b)*16384 + xi]);
        float a=X[xi*3], bb=X[xi*3+1], c=X[xi*3+2];
        v = f + a*a + bb*bb + c*c;
    }
    v = blockReduceT<0>(v);
    if (t == 0) atomicAdd(&g_accum[mode], v);
}

__global__ void k_final(float* out){
    if (threadIdx.x == 0){
        float a0 = g_accum[0] / (float)(NB*NPTS0);
        float a1 = g_accum[1] / (float)(NB*NPTS0);
        float a2 = g_accum[2] / (float)(NB*NNEW);
        float a3 = g_accum[3] / (float)(NB*NPTS0);
        out[0] = 0.1f*(a0 + a1) + 1.0f*(a2 + a3);
    }
}

// ---------------- host ----------------
extern "C" void kernel_launch(void* const* d_in, const int* in_sizes, int n_in,
                              void* d_out, int out_size){
    const float* points   = (const float*)d_in[0];
    const float* gt       = (const float*)d_in[1];
    const float* enc_w1   = (const float*)d_in[2];
    const float* enc_b1   = (const float*)d_in[3];
    const float* enc_w2   = (const float*)d_in[4];
    const float* enc_b2   = (const float*)d_in[5];
    const float* enc_w3   = (const float*)d_in[6];
    const float* enc_b3   = (const float*)d_in[7];
    const float* att_w1   = (const float*)d_in[8];
    const float* att_b1   = (const float*)d_in[9];
    const float* att_w2   = (const float*)d_in[10];
    const float* att_b2   = (const float*)d_in[11];
    const float* lstm_wih = (const float*)d_in[12];
    const float* lstm_whh = (const float*)d_in[13];
    const float* lstm_bih = (const float*)d_in[14];
    const float* lstm_bhh = (const float*)d_in[15];
    const float* ref_w1   = (const float*)d_in[16];
    const float* ref_b1   = (const float*)d_in[17];
    const float* ref_w2   = (const float*)d_in[18];
    const float* ref_b2   = (const float*)d_in[19];

    const int SM2 = (64*65 + 64*128)*4;     // 49408
    const int SM3 = (128*130 + 128*64)*4;   // 99328
    cudaFuncSetAttribute(k_enc2, cudaFuncAttributeMaxDynamicSharedMemorySize, SM2);
    cudaFuncSetAttribute(k_enc3, cudaFuncAttributeMaxDynamicSharedMemorySize, SM3);

    k_init<<<256,1024>>>(points);

    int encoded = 0;
    for (int s=0; s<STEPS; s++){
        int N   = NPTS0 + NEWP*s;
        int seg = N - encoded;
        int e0  = encoded;
        dim3 g1(seg/64, NB);        k_enc1<<<g1,256>>>(e0, enc_w1, enc_b1, att_w1);
        dim3 g2(seg/64, NB);        k_enc2<<<g2,256,SM2>>>(enc_w2, enc_b2);
        dim3 g3(seg/128, 4, NB);    k_enc3<<<g3,256,SM3>>>(enc_w3, enc_b3);
        encoded = N;
        dim3 ga(N/128, NB);         k_att<<<ga,128>>>(N, att_w1, att_b1, att_w2, att_b2);
        k_tail<<<NB,1024>>>(N, lstm_wih, lstm_whh, lstm_bih, lstm_bhh);
        k_refine<<<dim3(27,NB),128>>>(N, ref_w1, ref_b1, ref_w2, ref_b2);
    }
    k_cham2<<<dim3(23,6,16),128>>>(gt);
    k_chamsum<<<dim3(45,NB,4),256>>>(gt);
    k_final<<<1,32>>>((float*)d_out);
}

// round 6
// speedup vs baseline: 2.1027x; 1.2393x over previous
#include <cuda_runtime.h>
#include <math.h>

#define NB 4
#define NPTS0 4096
#define STEPS 10
#define NEWP 1152
#define GDIM 256
#define HDIM 128
#define KSEL 64
#define NMAX (NPTS0 + STEPS*NEWP)   // 15616
#define NNEW (STEPS*NEWP)           // 11520
#define MAXE 15                     // ceil(14464/1024)

typedef unsigned long long ull;

// ---------------- device state (no allocations allowed) ----------------
__device__ __align__(16) float g_canvas[NB*NMAX*3];
__device__ __align__(16) float g_h1[NB*4096*64];
__device__ __align__(16) float g_h2[NB*4096*128];
__device__ __align__(16) float g_pre[NB*128*NMAX];    // layout [b][j][i]
__device__ float g_gfeat[NB*GDIM];
__device__ float g_h[2][NB*HDIM];     // double-buffered by step parity
__device__ float g_c[2][NB*HDIM];
__device__ float g_ctr[NB*8];         // [b][0:3]=center, [3:6]=patch_feat
__device__ float g_base[NB*128];
__device__ float g_scores[NB*NMAX];
__device__ unsigned g_xmin[4*NB*16384];
__device__ float g_accum[4];

// ---------------- packed f32x2 helpers (FFMA2 path) ----------------
__device__ __forceinline__ ull pk(float lo, float hi){
    ull r; asm("mov.b64 %0,{%1,%2};" : "=l"(r) : "f"(lo), "f"(hi)); return r;
}
__device__ __forceinline__ void upk(ull v, float& lo, float& hi){
    asm("mov.b64 {%0,%1},%2;" : "=f"(lo), "=f"(hi) : "l"(v));
}
__device__ __forceinline__ ull fma2(ull a, ull b, ull c){
    ull d; asm("fma.rn.f32x2 %0,%1,%2,%3;" : "=l"(d) : "l"(a), "l"(b), "l"(c)); return d;
}
__device__ __forceinline__ ull mul2(ull a, ull b){
    ull d; asm("mul.rn.f32x2 %0,%1,%2;" : "=l"(d) : "l"(a), "l"(b)); return d;
}

__device__ __forceinline__ void atomicMaxF(float* addr, float val){
    int* ai = (int*)addr;
    int old = *ai;
    while (__int_as_float(old) < val){
        int assumed = old;
        old = atomicCAS(ai, assumed, __float_as_int(val));
        if (old == assumed) break;
    }
}

// float <-> order-preserving sortable uint
__device__ __forceinline__ unsigned f2s(float f){
    unsigned u = __float_as_uint(f);
    return u ^ ((unsigned)(((int)u) >> 31) | 0x80000000u);
}
__device__ __forceinline__ float s2f(unsigned s){
    unsigned u = (s & 0x80000000u) ? (s ^ 0x80000000u) : ~s;
    return __uint_as_float(u);
}

// OP=0 sum, OP=1 max. All threads participate; result broadcast.
template<int OP>
__device__ __forceinline__ float blockReduceT(float v){
    __shared__ float buf[32];
    #pragma unroll
    for (int o=16;o;o>>=1){
        float other = __shfl_down_sync(0xffffffffu, v, o);
        v = OP ? fmaxf(v, other) : v + other;
    }
    int w = threadIdx.x >> 5, l = threadIdx.x & 31, nw = blockDim.x >> 5;
    __syncthreads();
    if (l == 0) buf[w] = v;
    __syncthreads();
    if (w == 0){
        v = (l < nw) ? buf[l] : (OP ? -INFINITY : 0.f);
        #pragma unroll
        for (int o=16;o;o>>=1){
            float other = __shfl_down_sync(0xffffffffu, v, o);
            v = OP ? fmaxf(v, other) : v + other;
        }
        if (l == 0) buf[0] = v;
    }
    __syncthreads();
    return buf[0];
}

// ---------------- init ----------------
__global__ void k_init(const float* __restrict__ pts){
    int idx = blockIdx.x*blockDim.x + threadIdx.x;
    int total = NB*NPTS0*3;
    if (idx < total){
        int b = idx/(NPTS0*3); int r = idx%(NPTS0*3);
        g_canvas[b*NMAX*3 + r] = pts[idx];
    }
    if (idx < NB*HDIM){ g_h[0][idx]=0.f; g_c[0][idx]=0.f; }
    if (idx < NB*GDIM) g_gfeat[idx] = -INFINITY;
    if (idx < 4) g_accum[idx]=0.f;
    if (idx < 4*NB*16384) g_xmin[idx] = 0xFFFFFFFFu;
}

// ---------------- encoder layer1 + attention "pre" cache ----------------
__global__ void k_enc1(int e0,
                       const float* __restrict__ w1, const float* __restrict__ b1,
                       const float* __restrict__ aw1){
    int b = blockIdx.y, t = threadIdx.x;
    int il = blockIdx.x*64 + (t>>2);
    int gi = e0 + il;
    int part = t & 3;
    const float* p = &g_canvas[(b*NMAX+gi)*3];
    float x = p[0], y = p[1], z = p[2];
    float h[16];
    #pragma unroll
    for (int j=0;j<16;j++){
        int c = part*16 + j;
        float v = b1[c] + x*w1[c] + y*w1[64+c] + z*w1[128+c];
        h[j] = fmaxf(v, 0.f);
    }
    float* o = &g_h1[(b*4096 + il)*64 + part*16];
    #pragma unroll
    for (int q=0;q<4;q++)
        ((float4*)o)[q] = make_float4(h[4*q],h[4*q+1],h[4*q+2],h[4*q+3]);
    #pragma unroll
    for (int j=0;j<32;j++){
        int c = part*32 + j;
        float v = x*aw1[c] + y*aw1[128+c] + z*aw1[256+c];
        g_pre[(b*128 + c)*NMAX + gi] = v;
    }
}

// ---------------- encoder layer2 (packed FFMA2, W from L1) ----------------
// grid (seg/64, NB), 256 threads = 16ty x 16tx, tile 4pts x 8cols
__global__ void k_enc2(const float* __restrict__ w2, const float* __restrict__ b2){
    extern __shared__ float sm[];
    float* sA = sm;            // [64 k][65]
    int b = blockIdx.y, t = threadIdx.x;
    int p0 = blockIdx.x*64;
    for (int q=t; q<64*16; q+=256){
        int pt = q>>4, k4 = (q&15)<<2;
        float4 v = *(const float4*)&g_h1[(b*4096+p0+pt)*64 + k4];
        sA[(k4  )*65+pt]=v.x; sA[(k4+1)*65+pt]=v.y;
        sA[(k4+2)*65+pt]=v.z; sA[(k4+3)*65+pt]=v.w;
    }
    __syncthreads();
    int ty = t>>4, tx = t&15;
    ull acc[4][4];
    #pragma unroll
    for (int i=0;i<4;i++)
        #pragma unroll
        for (int j=0;j<4;j++) acc[i][j]=0ull;
    #pragma unroll 4
    for (int k=0;k<64;k++){
        ull ad[4];
        #pragma unroll
        for (int i=0;i<4;i++){ float a = sA[k*65+4*ty+i]; ad[i] = pk(a,a); }
        float4 wa = __ldg((const float4*)&w2[k*128 + 8*tx]);
        float4 wb = __ldg((const float4*)&w2[k*128 + 8*tx + 4]);
        ull wp[4] = { pk(wa.x,wa.y), pk(wa.z,wa.w), pk(wb.x,wb.y), pk(wb.z,wb.w) };
        #pragma unroll
        for (int i=0;i<4;i++)
            #pragma unroll
            for (int j=0;j<4;j++) acc[i][j] = fma2(ad[i], wp[j], acc[i][j]);
    }
    float bb[8];
    #pragma unroll
    for (int j=0;j<8;j++) bb[j] = b2[8*tx+j];
    #pragma unroll
    for (int i=0;i<4;i++){
        int pt = p0 + 4*ty + i;
        float r[8];
        #pragma unroll
        for (int j=0;j<4;j++){
            float lo,hi; upk(acc[i][j], lo, hi);
            r[2*j]   = fmaxf(lo + bb[2*j],   0.f);
            r[2*j+1] = fmaxf(hi + bb[2*j+1], 0.f);
        }
        *(float4*)&g_h2[(b*4096+pt)*128 + 8*tx]     = make_float4(r[0],r[1],r[2],r[3]);
        *(float4*)&g_h2[(b*4096+pt)*128 + 8*tx + 4] = make_float4(r[4],r[5],r[6],r[7]);
    }
}

// ---------------- encoder layer3 + running max (packed FFMA2, W from L1) ----
// grid (seg/128, 4 colblocks, NB), 256 threads = 16ty(8pts) x 16tx(4cols)
__global__ void k_enc3(const float* __restrict__ w3, const float* __restrict__ b3){
    extern __shared__ float sm[];
    float* sA = sm;              // [128 k][130]
    int b = blockIdx.z, cb = blockIdx.y, t = threadIdx.x;
    int p0 = blockIdx.x*128;
    for (int q=t; q<128*32; q+=256){
        int pt = q>>5, k4 = (q&31)<<2;
        float4 v = *(const float4*)&g_h2[(b*4096+p0+pt)*128 + k4];
        sA[(k4  )*130+pt]=v.x; sA[(k4+1)*130+pt]=v.y;
        sA[(k4+2)*130+pt]=v.z; sA[(k4+3)*130+pt]=v.w;
    }
    __syncthreads();
    int ty = t>>4, tx = t&15;
    ull acc[4][4];   // [pt-pair][col]
    #pragma unroll
    for (int i=0;i<4;i++)
        #pragma unroll
        for (int j=0;j<4;j++) acc[i][j]=0ull;
    #pragma unroll 4
    for (int k=0;k<128;k++){
        ull ap[4];
        #pragma unroll
        for (int i=0;i<4;i++) ap[i] = *(ull*)&sA[k*130 + 8*ty + 2*i];
        float4 w = __ldg((const float4*)&w3[k*256 + cb*64 + 4*tx]);
        ull wd[4] = { pk(w.x,w.x), pk(w.y,w.y), pk(w.z,w.z), pk(w.w,w.w) };
        #pragma unroll
        for (int i=0;i<4;i++)
            #pragma unroll
            for (int j=0;j<4;j++) acc[i][j] = fma2(ap[i], wd[j], acc[i][j]);
    }
    float m[4];
    #pragma unroll
    for (int j=0;j<4;j++){
        float best = -INFINITY;
        #pragma unroll
        for (int i=0;i<4;i++){
            float lo,hi; upk(acc[i][j], lo, hi);
            best = fmaxf(best, fmaxf(lo,hi));
        }
        m[j] = best + b3[cb*64 + 4*tx + j];
    }
    __syncthreads();
    float* red = sA;   // reuse
    #pragma unroll
    for (int j=0;j<4;j++) red[ty*64 + 4*tx + j] = m[j];
    __syncthreads();
    if (t < 64){
        float v = red[t];
        #pragma unroll
        for (int r=1;r<16;r++) v = fmaxf(v, red[r*64 + t]);
        atomicMaxF(&g_gfeat[b*GDIM + cb*64 + t], v);
    }
}

// ---------------- attention base (per step, per batch) ----------------
// grid NB, 1024 threads: 8 k-groups x 128 outputs
__global__ void k_attbase(int r,
                          const float* __restrict__ aw1, const float* __restrict__ ab1){
    __shared__ float part[8][128];
    int b = blockIdx.x, t = threadIdx.x;
    int kg = t >> 7, tt = t & 127;
    const float* gf = &g_gfeat[b*GDIM];
    const float* hh = &g_h[r][b*HDIM];
    float s = 0.f;
    int k0 = kg*48;
    #pragma unroll 4
    for (int k=k0; k<k0+48; k++){
        float a = (k < 256) ? gf[k] : hh[k-256];
        s += a * aw1[(3+k)*128 + tt];
    }
    part[kg][tt] = s;
    __syncthreads();
    if (t < 128){
        float v = ab1[t];
        #pragma unroll
        for (int q=0;q<8;q++) v += part[q][t];
        g_base[b*128 + t] = v;
    }
}

// ---------------- attention scores (factorized, 2 pts/thread) ----------------
// grid (ceil(N/256), NB), 128 threads
__global__ void k_att(int N,
                      const float* __restrict__ aw2, const float* __restrict__ ab2){
    __shared__ float base[128], w2s[128];
    int b = blockIdx.y, t = threadIdx.x;
    base[t] = g_base[b*128 + t];
    w2s[t]  = aw2[t];
    __syncthreads();
    int i0 = blockIdx.x*256 + 2*t;
    if (i0 >= N) return;
    const float* pr = &g_pre[(b*128)*NMAX + i0];
    float a0 = 0.f, a1 = 0.f;
    #pragma unroll 4
    for (int j=0;j<128;j++){
        ull pv = *(const ull*)&pr[j*NMAX];
        float lo,hi; upk(pv, lo, hi);
        float bj = base[j], wj = w2s[j];
        a0 += fmaxf(lo + bj, 0.f) * wj;
        a1 += fmaxf(hi + bj, 0.f) * wj;
    }
    float c = ab2[0];
    g_scores[b*NMAX + i0]     = c + a0;
    g_scores[b*NMAX + i0 + 1] = c + a1;
}

// ---------------- per-batch tail: softmax/center/top-K -> ctr+pf ----------------
// grid NB, 1024 threads. Register-resident scores & dist bits.
__global__ void __launch_bounds__(1024) k_tail(int N){
    __shared__ unsigned s_hist[256];
    __shared__ int s_ibc[4];
    int b = blockIdx.x, t = threadIdx.x;
    const float* sc = &g_scores[b*NMAX];
    const float* cv = &g_canvas[b*NMAX*3];

    float vs[MAXE]; unsigned du[MAXE];
    float mx = -INFINITY;
    #pragma unroll
    for (int e=0;e<MAXE;e++){
        int i = t + e*1024;
        if (i < N){ vs[e] = sc[i]; mx = fmaxf(mx, vs[e]); }
    }
    mx = blockReduceT<1>(mx);
    float es=0.f, cx=0.f, cy=0.f, cz=0.f;
    #pragma unroll
    for (int e=0;e<MAXE;e++){
        int i = t + e*1024;
        if (i < N){
            float ex = expf(vs[e]-mx);
            es += ex;
            cx += ex*cv[3*i]; cy += ex*cv[3*i+1]; cz += ex*cv[3*i+2];
        }
    }
    es = blockReduceT<0>(es);
    cx = blockReduceT<0>(cx); cy = blockReduceT<0>(cy); cz = blockReduceT<0>(cz);
    float ctr0 = cx/es, ctr1 = cy/es, ctr2 = cz/es;
    if (t == 0){ g_ctr[b*8+0]=ctr0; g_ctr[b*8+1]=ctr1; g_ctr[b*8+2]=ctr2; }
    #pragma unroll
    for (int e=0;e<MAXE;e++){
        int i = t + e*1024;
        if (i < N){
            float dx=cv[3*i]-ctr0, dy=cv[3*i+1]-ctr1, dz=cv[3*i+2]-ctr2;
            du[e] = __float_as_uint(dx*dx + dy*dy + dz*dz);
        }
    }
    // radix select K-th smallest (dist bits nonneg -> uint order)
    unsigned prefix = 0; int krem = KSEL;
    for (int rd=0; rd<4; rd++){
        int shift = 24 - 8*rd;
        unsigned maskhi = (rd==0) ? 0u : (0xFFFFFFFFu << (shift+8));
        __syncthreads();
        if (t < 256) s_hist[t] = 0u;
        __syncthreads();
        #pragma unroll
        for (int e=0;e<MAXE;e++){
            int i = t + e*1024;
            if (i < N){
                unsigned u = du[e];
                if ((u & maskhi) == prefix) atomicAdd(&s_hist[(u>>shift)&255], 1u);
            }
        }
        __syncthreads();
        if (t == 0){
            unsigned cum = 0; int sel = 255;
            for (int bin=0;bin<256;bin++){
                unsigned c = s_hist[bin];
                if (cum + c >= (unsigned)krem){ sel = bin; break; }
                cum += c;
            }
            s_ibc[0] = sel; s_ibc[1] = krem - (int)cum;
        }
        __syncthreads();
        prefix |= ((unsigned)s_ibc[0]) << shift;
        krem = s_ibc[1];
    }
    __syncthreads();
    if (t == 0) s_ibc[2] = 0;
    __syncthreads();
    float sx=0.f, sy=0.f, sz=0.f;
    #pragma unroll
    for (int e=0;e<MAXE;e++){
        int i = t + e*1024;
        if (i < N){
            unsigned u = du[e];
            bool take = false;
            if (u < prefix) take = true;
            else if (u == prefix){
                int pos = atomicAdd(&s_ibc[2], 1);
                if (pos < krem) take = true;
            }
            if (take){ sx += cv[3*i]; sy += cv[3*i+1]; sz += cv[3*i+2]; }
        }
    }
    sx = blockReduceT<0>(sx); sy = blockReduceT<0>(sy); sz = blockReduceT<0>(sz);
    if (t == 0){
        g_ctr[b*8+3] = sx/(float)KSEL - ctr0;
        g_ctr[b*8+4] = sy/(float)KSEL - ctr1;
        g_ctr[b*8+5] = sz/(float)KSEL - ctr2;
    }
}

// ---------------- refine: LSTM (redundant per block) + 2-layer MLP + scatter --
// grid (7, NB), 512 threads. r = read parity for h/c, writes 1-r (block x==0).
__global__ void k_refine(int N, int r,
    const float* __restrict__ wih, const float* __restrict__ whh,
    const float* __restrict__ bih, const float* __restrict__ bhh,
    const float* __restrict__ rw1, const float* __restrict__ rb1,
    const float* __restrict__ rw2, const float* __restrict__ rb2){
    __shared__ float s_in[262], s_hold[128], s_h[128], s_r[128], s_g[512];
    int b = blockIdx.y, t = threadIdx.x;
    if (t < 256) s_in[t] = g_gfeat[b*GDIM + t];
    else if (t < 262) s_in[t] = g_ctr[b*8 + (t-256)];
    if (t < 128) s_hold[t] = g_h[r][b*HDIM + t];
    __syncthreads();
    // gates: one output per thread (j = t), coalesced weight reads
    {
        float g = bih[t] + bhh[t];
        #pragma unroll 8
        for (int k=0;k<262;k++) g += s_in[k]*__ldg(&wih[k*512 + t]);
        #pragma unroll 8
        for (int k=0;k<128;k++) g += s_hold[k]*__ldg(&whh[k*512 + t]);
        s_g[t] = g;
    }
    __syncthreads();
    if (t < 128){
        float gi = s_g[t], gf = s_g[128+t], gg = s_g[256+t], go = s_g[384+t];
        float si = 1.f/(1.f+expf(-gi));
        float sf = 1.f/(1.f+expf(-gf));
        float so = 1.f/(1.f+expf(-go));
        float cn = sf*g_c[r][b*HDIM+t] + si*tanhf(gg);
        float hn = so*tanhf(cn);
        if (blockIdx.x == 0){ g_c[1-r][b*HDIM+t] = cn; g_h[1-r][b*HDIM+t] = hn; }
        s_h[t] = hn;
    }
    __syncthreads();
    if (t < 128){
        float v = rb1[t];
        #pragma unroll 4
        for (int k=0;k<128;k++) v += s_h[k]*rw1[k*128 + t];
        s_r[t] = fmaxf(v, 0.f);
    }
    __syncthreads();
    int j = blockIdx.x*512 + t;
    if (j < NEWP*3){
        float v = rb2[j];
        #pragma unroll 8
        for (int k=0;k<128;k++) v += s_r[k]*__ldg(&rw2[k*(NEWP*3) + j]);
        int d = j % 3, pt = j / 3;
        g_canvas[(b*NMAX + N + pt)*3 + d] = v*0.02f + g_ctr[b*8 + d];
    }
}

// ---------------- chamfer: packed-FFMA2 pairwise min (full chip) ----------------
__global__ void k_cham2(const float* __restrict__ gt){
    __shared__ __align__(16) float s_yx[128];
    __shared__ __align__(16) float s_yy[128];
    __shared__ __align__(16) float s_yz[128];
    __shared__ __align__(16) float s_n[128];
    int z = blockIdx.z; int mode = z >> 2; int b = z & 3;
    const float* cin = &g_canvas[b*NMAX*3];
    const float* gb  = &gt[b*NPTS0*3];
    const float *X, *Y; int nx, ny;
    if (mode == 0){ X=cin;          Y=gb;          nx=NPTS0; ny=NPTS0; }
    else if (mode == 1){ X=gb;      Y=cin;         nx=NPTS0; ny=NPTS0; }
    else if (mode == 2){ X=cin+NPTS0*3; Y=gb;      nx=NNEW;  ny=NPTS0; }
    else { X=gb;          Y=cin+NPTS0*3;           nx=NPTS0; ny=NNEW;  }
    int x0 = blockIdx.x*512;
    int y0 = blockIdx.y*2048;
    if (x0 >= nx || y0 >= ny) return;
    int yend = min(y0 + 2048, ny);
    int t = threadIdx.x;

    ull xd[4][3]; bool val[4]; float me[4], mo[4];
    #pragma unroll
    for (int i=0;i<4;i++){
        int xi = x0 + i*128 + t;
        val[i] = xi < nx;
        int cl = val[i] ? xi : 0;
        float a=X[cl*3], bb=X[cl*3+1], c=X[cl*3+2];
        xd[i][0]=pk(a,a); xd[i][1]=pk(bb,bb); xd[i][2]=pk(c,c);
        me[i]=INFINITY; mo[i]=INFINITY;
    }
    ull c_m2 = pk(-2.f,-2.f);

    for (int yb=y0; yb<yend; yb+=128){
        __syncthreads();
        {
            int yi = yb + t;
            float a=Y[yi*3], bb=Y[yi*3+1], c=Y[yi*3+2];
            s_yx[t]=a; s_yy[t]=bb; s_yz[t]=c;
            s_n[t]=a*a + bb*bb + c*c;
        }
        __syncthreads();
        #pragma unroll 4
        for (int j=0;j<64;j++){
            ull yx = ((ull*)s_yx)[j];
            ull yy = ((ull*)s_yy)[j];
            ull yz = ((ull*)s_yz)[j];
            ull nn = ((ull*)s_n)[j];
            #pragma unroll
            for (int i=0;i<4;i++){
                ull dot = fma2(xd[i][2], yz, fma2(xd[i][1], yy, mul2(xd[i][0], yx)));
                ull d   = fma2(dot, c_m2, nn);
                float lo,hi; upk(d, lo, hi);
                me[i] = fminf(me[i], lo);
                mo[i] = fminf(mo[i], hi);
            }
        }
    }
    #pragma unroll
    for (int i=0;i<4;i++){
        if (val[i]){
            float m = fminf(me[i], mo[i]);
            atomicMin(&g_xmin[(mode*NB + b)*16384 + x0 + i*128 + t], f2s(m));
        }
    }
}

// sum pass: accum[mode] = sum_x (|x|^2 + min-part)
__global__ void k_chamsum(const float* __restrict__ gt){
    int mode = blockIdx.z, b = blockIdx.y, t = threadIdx.x;
    const float* cin = &g_canvas[b*NMAX*3];
    const float* gb  = &gt[b*NPTS0*3];
    const float* X; int nx;
    if (mode == 0){ X=cin; nx=NPTS0; }
    else if (mode == 1){ X=gb; nx=NPTS0; }
    else if (mode == 2){ X=cin+NPTS0*3; nx=NNEW; }
    else { X=gb; nx=NPTS0; }
    int xi = blockIdx.x*256 + t;
    float v = 0.f;
    if (xi < nx){
        float f = s2f(g_xmin[(mode*NB + b)*16384 + xi]);
        float a=X[xi*3], bb=X[xi*3+1], c=X[xi*3+2];
        v = f + a*a + bb*bb + c*c;
    }
    v = blockReduceT<0>(v);
    if (t == 0) atomicAdd(&g_accum[mode], v);
}

__global__ void k_final(float* out){
    if (threadIdx.x == 0){
        float a0 = g_accum[0] / (float)(NB*NPTS0);
        float a1 = g_accum[1] / (float)(NB*NPTS0);
        float a2 = g_accum[2] / (float)(NB*NNEW);
        float a3 = g_accum[3] / (float)(NB*NPTS0);
        out[0] = 0.1f*(a0 + a1) + 1.0f*(a2 + a3);
    }
}

// ---------------- host ----------------
extern "C" void kernel_launch(void* const* d_in, const int* in_sizes, int n_in,
                              void* d_out, int out_size){
    const float* points   = (const float*)d_in[0];
    const float* gt       = (const float*)d_in[1];
    const float* enc_w1   = (const float*)d_in[2];
    const float* enc_b1   = (const float*)d_in[3];
    const float* enc_w2   = (const float*)d_in[4];
    const float* enc_b2   = (const float*)d_in[5];
    const float* enc_w3   = (const float*)d_in[6];
    const float* enc_b3   = (const float*)d_in[7];
    const float* att_w1   = (const float*)d_in[8];
    const float* att_b1   = (const float*)d_in[9];
    const float* att_w2   = (const float*)d_in[10];
    const float* att_b2   = (const float*)d_in[11];
    const float* lstm_wih = (const float*)d_in[12];
    const float* lstm_whh = (const float*)d_in[13];
    const float* lstm_bih = (const float*)d_in[14];
    const float* lstm_bhh = (const float*)d_in[15];
    const float* ref_w1   = (const float*)d_in[16];
    const float* ref_b1   = (const float*)d_in[17];
    const float* ref_w2   = (const float*)d_in[18];
    const float* ref_b2   = (const float*)d_in[19];

    const int SM2 = 64*65*4;     // 16640
    const int SM3 = 128*130*4;   // 66560
    cudaFuncSetAttribute(k_enc2, cudaFuncAttributeMaxDynamicSharedMemorySize, SM2);
    cudaFuncSetAttribute(k_enc3, cudaFuncAttributeMaxDynamicSharedMemorySize, SM3);

    k_init<<<256,1024>>>(points);

    int encoded = 0;
    for (int s=0; s<STEPS; s++){
        int N   = NPTS0 + NEWP*s;
        int seg = N - encoded;
        int e0  = encoded;
        int r   = s & 1;
        dim3 g1(seg/64, NB);        k_enc1<<<g1,256>>>(e0, enc_w1, enc_b1, att_w1);
        dim3 g2(seg/64, NB);        k_enc2<<<g2,256,SM2>>>(enc_w2, enc_b2);
        dim3 g3(seg/128, 4, NB);    k_enc3<<<g3,256,SM3>>>(enc_w3, enc_b3);
        encoded = N;
        k_attbase<<<NB,1024>>>(r, att_w1, att_b1);
        dim3 ga((N+255)/256, NB);   k_att<<<ga,128>>>(N, att_w2, att_b2);
        k_tail<<<NB,1024>>>(N);
        k_refine<<<dim3(7,NB),512>>>(N, r, lstm_wih, lstm_whh, lstm_bih, lstm_bhh,
                                     ref_w1, ref_b1, ref_w2, ref_b2);
    }
    k_cham2<<<dim3(23,6,16),128>>>(gt);
    k_chamsum<<<dim3(45,NB,4),256>>>(gt);
    k_final<<<1,32>>>((float*)d_out);
}

// round 7
// speedup vs baseline: 2.1715x; 1.0327x over previous
#include <cuda_runtime.h>
#include <math.h>

#define NB 4
#define NPTS0 4096
#define STEPS 10
#define NEWP 1152
#define GDIM 256
#define HDIM 128
#define KSEL 64
#define NMAX (NPTS0 + STEPS*NEWP)   // 15616
#define NNEW (STEPS*NEWP)           // 11520
#define MAXE 15                     // ceil(14464/1024)

typedef unsigned long long ull;

// ---------------- device state (no allocations allowed) ----------------
__device__ __align__(16) float g_canvas[NB*NMAX*3];
__device__ __align__(16) float g_h2[NB*4096*128];
__device__ __align__(16) float g_pre[NB*128*NMAX];    // layout [b][j][i]
__device__ float g_gfeat[NB*GDIM];
__device__ float g_h[2][NB*HDIM];     // double-buffered by step parity
__device__ float g_c[2][NB*HDIM];
__device__ float g_ctr[NB*8];         // [b][0:3]=center, [3:6]=patch_feat
__device__ float g_scores[NB*NMAX];
__device__ unsigned g_xmin[4*NB*16384];
__device__ float g_accum[4];
__device__ int   g_flag[STEPS*NB];

// ---------------- packed f32x2 helpers (FFMA2 path) ----------------
__device__ __forceinline__ ull pk(float lo, float hi){
    ull r; asm("mov.b64 %0,{%1,%2};" : "=l"(r) : "f"(lo), "f"(hi)); return r;
}
__device__ __forceinline__ void upk(ull v, float& lo, float& hi){
    asm("mov.b64 {%0,%1},%2;" : "=f"(lo), "=f"(hi) : "l"(v));
}
__device__ __forceinline__ ull fma2(ull a, ull b, ull c){
    ull d; asm("fma.rn.f32x2 %0,%1,%2,%3;" : "=l"(d) : "l"(a), "l"(b), "l"(c)); return d;
}
__device__ __forceinline__ ull mul2(ull a, ull b){
    ull d; asm("mul.rn.f32x2 %0,%1,%2;" : "=l"(d) : "l"(a), "l"(b)); return d;
}

__device__ __forceinline__ void atomicMaxF(float* addr, float val){
    int* ai = (int*)addr;
    int old = *ai;
    while (__int_as_float(old) < val){
        int assumed = old;
        old = atomicCAS(ai, assumed, __float_as_int(val));
        if (old == assumed) break;
    }
}

// float <-> order-preserving sortable uint
__device__ __forceinline__ unsigned f2s(float f){
    unsigned u = __float_as_uint(f);
    return u ^ ((unsigned)(((int)u) >> 31) | 0x80000000u);
}
__device__ __forceinline__ float s2f(unsigned s){
    unsigned u = (s & 0x80000000u) ? (s ^ 0x80000000u) : ~s;
    return __uint_as_float(u);
}

// OP=0 sum, OP=1 max. All threads participate; result broadcast.
template<int OP>
__device__ __forceinline__ float blockReduceT(float v){
    __shared__ float buf[32];
    #pragma unroll
    for (int o=16;o;o>>=1){
        float other = __shfl_down_sync(0xffffffffu, v, o);
        v = OP ? fmaxf(v, other) : v + other;
    }
    int w = threadIdx.x >> 5, l = threadIdx.x & 31, nw = blockDim.x >> 5;
    __syncthreads();
    if (l == 0) buf[w] = v;
    __syncthreads();
    if (w == 0){
        v = (l < nw) ? buf[l] : (OP ? -INFINITY : 0.f);
        #pragma unroll
        for (int o=16;o;o>>=1){
            float other = __shfl_down_sync(0xffffffffu, v, o);
            v = OP ? fmaxf(v, other) : v + other;
        }
        if (l == 0) buf[0] = v;
    }
    __syncthreads();
    return buf[0];
}

// ---------------- init ----------------
__global__ void k_init(const float* __restrict__ pts){
    int idx = blockIdx.x*blockDim.x + threadIdx.x;
    int total = NB*NPTS0*3;
    if (idx < total){
        int b = idx/(NPTS0*3); int r = idx%(NPTS0*3);
        g_canvas[b*NMAX*3 + r] = pts[idx];
    }
    if (idx < NB*HDIM){ g_h[0][idx]=0.f; g_c[0][idx]=0.f; }
    if (idx < NB*GDIM) g_gfeat[idx] = -INFINITY;
    if (idx < 4) g_accum[idx]=0.f;
    if (idx < STEPS*NB) g_flag[idx]=0;
    if (idx < 4*NB*16384) g_xmin[idx] = 0xFFFFFFFFu;
}

// ---------------- fused encoder layer1+layer2 + attention "pre" cache ----------
// grid (seg/64, NB), 256 threads. Phase A: enc1 into smem sA (transposed) + g_pre.
// Phase B: enc2 GEMM (16ty x 16tx, tile 4pts x 8cols) -> g_h2 (segment-local rows).
__global__ void k_enc12(int e0,
                        const float* __restrict__ w1, const float* __restrict__ b1,
                        const float* __restrict__ aw1,
                        const float* __restrict__ w2, const float* __restrict__ b2){
    extern __shared__ float sm[];
    float* sA  = sm;            // [64 k][65]
    float* sW2 = sm + 64*65;    // [64 k][128]
    int b = blockIdx.y, t = threadIdx.x;
    int p0 = blockIdx.x*64;     // segment-local base
    for (int q=t; q<2048; q+=256) ((float4*)sW2)[q] = ((const float4*)w2)[q];
    // Phase A: enc1
    {
        int il = t>>2;          // local point 0..63
        int gi = e0 + p0 + il;  // global canvas index
        int part = t & 3;
        const float* p = &g_canvas[(b*NMAX+gi)*3];
        float x = p[0], y = p[1], z = p[2];
        #pragma unroll
        for (int j=0;j<16;j++){
            int c = part*16 + j;
            float v = b1[c] + x*w1[c] + y*w1[64+c] + z*w1[128+c];
            sA[c*65 + il] = fmaxf(v, 0.f);
        }
        #pragma unroll
        for (int j=0;j<32;j++){
            int c = part*32 + j;
            float v = x*aw1[c] + y*aw1[128+c] + z*aw1[256+c];
            g_pre[(b*128 + c)*NMAX + gi] = v;
        }
    }
    __syncthreads();
    // Phase B: enc2
    int ty = t>>4, tx = t&15;
    ull acc[4][4];
    #pragma unroll
    for (int i=0;i<4;i++)
        #pragma unroll
        for (int j=0;j<4;j++) acc[i][j]=0ull;
    #pragma unroll 2
    for (int k=0;k<64;k++){
        ull ad[4];
        #pragma unroll
        for (int i=0;i<4;i++){ float a = sA[k*65+4*ty+i]; ad[i] = pk(a,a); }
        ull wp[4];
        #pragma unroll
        for (int j=0;j<4;j++) wp[j] = *(ull*)&sW2[k*128 + 8*tx + 2*j];
        #pragma unroll
        for (int i=0;i<4;i++)
            #pragma unroll
            for (int j=0;j<4;j++) acc[i][j] = fma2(ad[i], wp[j], acc[i][j]);
    }
    float bb[8];
    #pragma unroll
    for (int j=0;j<8;j++) bb[j] = b2[8*tx+j];
    #pragma unroll
    for (int i=0;i<4;i++){
        int pt = p0 + 4*ty + i;
        float r[8];
        #pragma unroll
        for (int j=0;j<4;j++){
            float lo,hi; upk(acc[i][j], lo, hi);
            r[2*j]   = fmaxf(lo + bb[2*j],   0.f);
            r[2*j+1] = fmaxf(hi + bb[2*j+1], 0.f);
        }
        *(float4*)&g_h2[(b*4096+pt)*128 + 8*tx]     = make_float4(r[0],r[1],r[2],r[3]);
        *(float4*)&g_h2[(b*4096+pt)*128 + 8*tx + 4] = make_float4(r[4],r[5],r[6],r[7]);
    }
}

// ---------------- encoder layer3 + running max (R4 dual-smem version) --------
// grid (seg/128, 4 colblocks, NB), 256 threads = 16ty(8pts) x 16tx(4cols)
__global__ void k_enc3(const float* __restrict__ w3, const float* __restrict__ b3){
    extern __shared__ float sm[];
    float* sA = sm;              // [128 k][130]  (even stride -> aligned ull reads)
    float* sW = sm + 128*130;    // [128 k][64]
    int b = blockIdx.z, cb = blockIdx.y, t = threadIdx.x;
    int p0 = blockIdx.x*128;
    for (int q=t; q<128*32; q+=256){
        int pt = q>>5, k4 = (q&31)<<2;
        float4 v = *(const float4*)&g_h2[(b*4096+p0+pt)*128 + k4];
        sA[(k4  )*130+pt]=v.x; sA[(k4+1)*130+pt]=v.y;
        sA[(k4+2)*130+pt]=v.z; sA[(k4+3)*130+pt]=v.w;
    }
    for (int q=t; q<2048; q+=256){
        int k = q>>4, c4 = (q&15)<<2;
        *(float4*)&sW[k*64 + c4] = *(const float4*)&w3[k*256 + cb*64 + c4];
    }
    __syncthreads();
    int ty = t>>4, tx = t&15;
    ull acc[4][4];   // [pt-pair][col]
    #pragma unroll
    for (int i=0;i<4;i++)
        #pragma unroll
        for (int j=0;j<4;j++) acc[i][j]=0ull;
    #pragma unroll 2
    for (int k=0;k<128;k++){
        ull ap[4];
        #pragma unroll
        for (int i=0;i<4;i++) ap[i] = *(ull*)&sA[k*130 + 8*ty + 2*i];
        float4 w = *(float4*)&sW[k*64 + 4*tx];
        ull wd[4] = { pk(w.x,w.x), pk(w.y,w.y), pk(w.z,w.z), pk(w.w,w.w) };
        #pragma unroll
        for (int i=0;i<4;i++)
            #pragma unroll
            for (int j=0;j<4;j++) acc[i][j] = fma2(ap[i], wd[j], acc[i][j]);
    }
    float m[4];
    #pragma unroll
    for (int j=0;j<4;j++){
        float best = -INFINITY;
        #pragma unroll
        for (int i=0;i<4;i++){
            float lo,hi; upk(acc[i][j], lo, hi);
            best = fmaxf(best, fmaxf(lo,hi));
        }
        m[j] = best + b3[cb*64 + 4*tx + j];
    }
    __syncthreads();
    float* red = sA;   // reuse
    #pragma unroll
    for (int j=0;j<4;j++) red[ty*64 + 4*tx + j] = m[j];
    __syncthreads();
    if (t < 64){
        float v = red[t];
        #pragma unroll
        for (int r=1;r<16;r++) v = fmaxf(v, red[r*64 + t]);
        atomicMaxF(&g_gfeat[b*GDIM + cb*64 + t], v);
    }
}

// ---------------- attention scores (base fused, 2 pts/thread) ----------------
// grid (ceil(N/512), NB), 256 threads
__global__ void k_att(int N, int r,
                      const float* __restrict__ aw1, const float* __restrict__ ab1,
                      const float* __restrict__ aw2, const float* __restrict__ ab2){
    __shared__ float s_part[2][128];
    __shared__ float s_base[128], s_w2[128];
    int b = blockIdx.y, t = threadIdx.x;
    int kg = t >> 7, tt = t & 127;
    {
        const float* gf = &g_gfeat[b*GDIM];
        const float* hh = &g_h[r][b*HDIM];
        float s = 0.f;
        int k0 = kg*192;
        #pragma unroll 4
        for (int k=k0; k<k0+192; k++){
            float a = (k < 256) ? gf[k] : hh[k-256];
            s += a * aw1[(3+k)*128 + tt];
        }
        s_part[kg][tt] = s;
    }
    __syncthreads();
    if (t < 128){
        s_base[t] = ab1[t] + s_part[0][t] + s_part[1][t];
        s_w2[t]   = aw2[t];
    }
    __syncthreads();
    int i0 = blockIdx.x*512 + 2*t;
    if (i0 >= N) return;
    const float* pr = &g_pre[(b*128)*NMAX + i0];
    float a0 = 0.f, a1 = 0.f;
    #pragma unroll 4
    for (int j=0;j<128;j++){
        ull pv = *(const ull*)&pr[j*NMAX];
        float lo,hi; upk(pv, lo, hi);
        float bj = s_base[j], wj = s_w2[j];
        a0 += fmaxf(lo + bj, 0.f) * wj;
        a1 += fmaxf(hi + bj, 0.f) * wj;
    }
    float c = ab2[0];
    g_scores[b*NMAX + i0]     = c + a0;
    g_scores[b*NMAX + i0 + 1] = c + a1;
}

// ---------------- fused tail + LSTM + refine ----------------
// grid (8, NB), 1024 threads. Block x==0: softmax/center/top-K/LSTM -> flag.
// Blocks x>0 spin on flag (all 32 blocks co-resident on 148 SMs -> safe).
// Then ALL blocks do the refine MLP (432 outputs each).
__global__ void __launch_bounds__(1024) k_tailref(int N, int r, int s,
    const float* __restrict__ wih, const float* __restrict__ whh,
    const float* __restrict__ bih, const float* __restrict__ bhh,
    const float* __restrict__ rw1, const float* __restrict__ rb1,
    const float* __restrict__ rw2, const float* __restrict__ rb2){
    __shared__ unsigned s_hist[256];
    __shared__ int s_ibc[4];
    __shared__ float s_in[262], s_g[512], s_hold[128];
    __shared__ float s_h2[128], s_r[128];
    int b = blockIdx.y, bx = blockIdx.x, t = threadIdx.x;
    int* flag = &g_flag[s*NB + b];

    if (bx == 0){
        const float* sc = &g_scores[b*NMAX];
        const float* cv = &g_canvas[b*NMAX*3];
        float vs[MAXE]; unsigned du[MAXE];
        float mx = -INFINITY;
        #pragma unroll
        for (int e=0;e<MAXE;e++){
            int i = t + e*1024;
            if (i < N){ vs[e] = sc[i]; mx = fmaxf(mx, vs[e]); }
        }
        mx = blockReduceT<1>(mx);
        float es=0.f, cx=0.f, cy=0.f, cz=0.f;
        #pragma unroll
        for (int e=0;e<MAXE;e++){
            int i = t + e*1024;
            if (i < N){
                float ex = expf(vs[e]-mx);
                es += ex;
                cx += ex*cv[3*i]; cy += ex*cv[3*i+1]; cz += ex*cv[3*i+2];
            }
        }
        es = blockReduceT<0>(es);
        cx = blockReduceT<0>(cx); cy = blockReduceT<0>(cy); cz = blockReduceT<0>(cz);
        float ctr0 = cx/es, ctr1 = cy/es, ctr2 = cz/es;
        #pragma unroll
        for (int e=0;e<MAXE;e++){
            int i = t + e*1024;
            if (i < N){
                float dx=cv[3*i]-ctr0, dy=cv[3*i+1]-ctr1, dz=cv[3*i+2]-ctr2;
                du[e] = __float_as_uint(dx*dx + dy*dy + dz*dz);
            }
        }
        unsigned prefix = 0; int krem = KSEL;
        for (int rd=0; rd<4; rd++){
            int shift = 24 - 8*rd;
            unsigned maskhi = (rd==0) ? 0u : (0xFFFFFFFFu << (shift+8));
            __syncthreads();
            if (t < 256) s_hist[t] = 0u;
            __syncthreads();
            #pragma unroll
            for (int e=0;e<MAXE;e++){
                int i = t + e*1024;
                if (i < N){
                    unsigned u = du[e];
                    if ((u & maskhi) == prefix) atomicAdd(&s_hist[(u>>shift)&255], 1u);
                }
            }
            __syncthreads();
            if (t == 0){
                unsigned cum = 0; int sel = 255;
                for (int bin=0;bin<256;bin++){
                    unsigned c = s_hist[bin];
                    if (cum + c >= (unsigned)krem){ sel = bin; break; }
                    cum += c;
                }
                s_ibc[0] = sel; s_ibc[1] = krem - (int)cum;
            }
            __syncthreads();
            prefix |= ((unsigned)s_ibc[0]) << shift;
            krem = s_ibc[1];
        }
        __syncthreads();
        if (t == 0) s_ibc[2] = 0;
        __syncthreads();
        float sx=0.f, sy=0.f, sz=0.f;
        #pragma unroll
        for (int e=0;e<MAXE;e++){
            int i = t + e*1024;
            if (i < N){
                unsigned u = du[e];
                bool take = false;
                if (u < prefix) take = true;
                else if (u == prefix){
                    int pos = atomicAdd(&s_ibc[2], 1);
                    if (pos < krem) take = true;
                }
                if (take){ sx += cv[3*i]; sy += cv[3*i+1]; sz += cv[3*i+2]; }
            }
        }
        sx = blockReduceT<0>(sx); sy = blockReduceT<0>(sy); sz = blockReduceT<0>(sz);
        float pf0 = sx/(float)KSEL - ctr0;
        float pf1 = sy/(float)KSEL - ctr1;
        float pf2 = sz/(float)KSEL - ctr2;
        if (t == 0){
            g_ctr[b*8+0]=ctr0; g_ctr[b*8+1]=ctr1; g_ctr[b*8+2]=ctr2;
            g_ctr[b*8+3]=pf0;  g_ctr[b*8+4]=pf1;  g_ctr[b*8+5]=pf2;
        }
        // LSTM
        if (t < 256) s_in[t] = g_gfeat[b*GDIM + t];
        else if (t == 256) s_in[256] = ctr0;
        else if (t == 257) s_in[257] = ctr1;
        else if (t == 258) s_in[258] = ctr2;
        else if (t == 259) s_in[259] = pf0;
        else if (t == 260) s_in[260] = pf1;
        else if (t == 261) s_in[261] = pf2;
        if (t < 128) s_hold[t] = g_h[r][b*HDIM + t];
        __syncthreads();
        if (t < 512){
            float g = bih[t] + bhh[t];
            #pragma unroll 8
            for (int k=0;k<262;k++) g += s_in[k]*__ldg(&wih[k*512 + t]);
            #pragma unroll 8
            for (int k=0;k<128;k++) g += s_hold[k]*__ldg(&whh[k*512 + t]);
            s_g[t] = g;
        }
        __syncthreads();
        if (t < 128){
            float gi = s_g[t], gf = s_g[128+t], gg = s_g[256+t], go = s_g[384+t];
            float si = 1.f/(1.f+expf(-gi));
            float sf = 1.f/(1.f+expf(-gf));
            float so = 1.f/(1.f+expf(-go));
            float cn = sf*g_c[r][b*HDIM+t] + si*tanhf(gg);
            float hn = so*tanhf(cn);
            g_c[1-r][b*HDIM+t] = cn;
            g_h[1-r][b*HDIM+t] = hn;
        }
        __threadfence();
        __syncthreads();
        if (t == 0) atomicExch(flag, 1);
    } else {
        if (t == 0){
            while (atomicAdd(flag, 0) == 0) __nanosleep(100);
        }
        __syncthreads();
    }
    // ---- refine (all blocks) ----
    if (t < 128) s_h2[t] = g_h[1-r][b*HDIM + t];
    __syncthreads();
    if (t < 128){
        float v = rb1[t];
        #pragma unroll 4
        for (int k=0;k<128;k++) v += s_h2[k]*rw1[k*128 + t];
        s_r[t] = fmaxf(v, 0.f);
    }
    __syncthreads();
    int j = bx*432 + t;
    if (t < 432 && j < NEWP*3){
        float v = rb2[j];
        #pragma unroll 8
        for (int k=0;k<128;k++) v += s_r[k]*__ldg(&rw2[k*(NEWP*3) + j]);
        int d = j % 3, pt = j / 3;
        g_canvas[(b*NMAX + N + pt)*3 + d] = v*0.02f + g_ctr[b*8 + d];
    }
}

// ---------------- chamfer: packed-FFMA2 pairwise min (full chip) ----------------
__global__ void k_cham2(const float* __restrict__ gt){
    __shared__ __align__(16) float s_yx[128];
    __shared__ __align__(16) float s_yy[128];
    __shared__ __align__(16) float s_yz[128];
    __shared__ __align__(16) float s_n[128];
    int z = blockIdx.z; int mode = z >> 2; int b = z & 3;
    const float* cin = &g_canvas[b*NMAX*3];
    const float* gb  = &gt[b*NPTS0*3];
    const float *X, *Y; int nx, ny;
    if (mode == 0){ X=cin;          Y=gb;          nx=NPTS0; ny=NPTS0; }
    else if (mode == 1){ X=gb;      Y=cin;         nx=NPTS0; ny=NPTS0; }
    else if (mode == 2){ X=cin+NPTS0*3; Y=gb;      nx=NNEW;  ny=NPTS0; }
    else { X=gb;          Y=cin+NPTS0*3;           nx=NPTS0; ny=NNEW;  }
    int x0 = blockIdx.x*512;
    int y0 = blockIdx.y*2048;
    if (x0 >= nx || y0 >= ny) return;
    int yend = min(y0 + 2048, ny);
    int t = threadIdx.x;

    ull xd[4][3]; bool val[4]; float me[4], mo[4];
    #pragma unroll
    for (int i=0;i<4;i++){
        int xi = x0 + i*128 + t;
        val[i] = xi < nx;
        int cl = val[i] ? xi : 0;
        float a=X[cl*3], bb=X[cl*3+1], c=X[cl*3+2];
        xd[i][0]=pk(a,a); xd[i][1]=pk(bb,bb); xd[i][2]=pk(c,c);
        me[i]=INFINITY; mo[i]=INFINITY;
    }
    ull c_m2 = pk(-2.f,-2.f);

    for (int yb=y0; yb<yend; yb+=128){
        __syncthreads();
        {
            int yi = yb + t;
            float a=Y[yi*3], bb=Y[yi*3+1], c=Y[yi*3+2];
            s_yx[t]=a; s_yy[t]=bb; s_yz[t]=c;
            s_n[t]=a*a + bb*bb + c*c;
        }
        __syncthreads();
        #pragma unroll 4
        for (int j=0;j<64;j++){
            ull yx = ((ull*)s_yx)[j];
            ull yy = ((ull*)s_yy)[j];
            ull yz = ((ull*)s_yz)[j];
            ull nn = ((ull*)s_n)[j];
            #pragma unroll
            for (int i=0;i<4;i++){
                ull dot = fma2(xd[i][2], yz, fma2(xd[i][1], yy, mul2(xd[i][0], yx)));
                ull d   = fma2(dot, c_m2, nn);
                float lo,hi; upk(d, lo, hi);
                me[i] = fminf(me[i], lo);
                mo[i] = fminf(mo[i], hi);
            }
        }
    }
    #pragma unroll
    for (int i=0;i<4;i++){
        if (val[i]){
            float m = fminf(me[i], mo[i]);
            atomicMin(&g_xmin[(mode*NB + b)*16384 + x0 + i*128 + t], f2s(m));
        }
    }
}

// sum pass: accum[mode] = sum_x (|x|^2 + min-part)
__global__ void k_chamsum(const float* __restrict__ gt){
    int mode = blockIdx.z, b = blockIdx.y, t = threadIdx.x;
    const float* cin = &g_canvas[b*NMAX*3];
    const float* gb  = &gt[b*NPTS0*3];
    const float* X; int nx;
    if (mode == 0){ X=cin; nx=NPTS0; }
    else if (mode == 1){ X=gb; nx=NPTS0; }
    else if (mode == 2){ X=cin+NPTS0*3; nx=NNEW; }
    else { X=gb; nx=NPTS0; }
    int xi = blockIdx.x*256 + t;
    float v = 0.f;
    if (xi < nx){
        float f = s2f(g_xmin[(mode*NB + b)*16384 + xi]);
        float a=X[xi*3], bb=X[xi*3+1], c=X[xi*3+2];
        v = f + a*a + bb*bb + c*c;
    }
    v = blockReduceT<0>(v);
    if (t == 0) atomicAdd(&g_accum[mode], v);
}

__global__ void k_final(float* out){
    if (threadIdx.x == 0){
        float a0 = g_accum[0] / (float)(NB*NPTS0);
        float a1 = g_accum[1] / (float)(NB*NPTS0);
        float a2 = g_accum[2] / (float)(NB*NNEW);
        float a3 = g_accum[3] / (float)(NB*NPTS0);
        out[0] = 0.1f*(a0 + a1) + 1.0f*(a2 + a3);
    }
}

// ---------------- host ----------------
extern "C" void kernel_launch(void* const* d_in, const int* in_sizes, int n_in,
                              void* d_out, int out_size){
    const float* points   = (const float*)d_in[0];
    const float* gt       = (const float*)d_in[1];
    const float* enc_w1   = (const float*)d_in[2];
    const float* enc_b1   = (const float*)d_in[3];
    const float* enc_w2   = (const float*)d_in[4];
    const float* enc_b2   = (const float*)d_in[5];
    const float* enc_w3   = (const float*)d_in[6];
    const float* enc_b3   = (const float*)d_in[7];
    const float* att_w1   = (const float*)d_in[8];
    const float* att_b1   = (const float*)d_in[9];
    const float* att_w2   = (const float*)d_in[10];
    const float* att_b2   = (const float*)d_in[11];
    const float* lstm_wih = (const float*)d_in[12];
    const float* lstm_whh = (const float*)d_in[13];
    const float* lstm_bih = (const float*)d_in[14];
    const float* lstm_bhh = (const float*)d_in[15];
    const float* ref_w1   = (const float*)d_in[16];
    const float* ref_b1   = (const float*)d_in[17];
    const float* ref_w2   = (const float*)d_in[18];
    const float* ref_b2   = (const float*)d_in[19];

    const int SM12 = (64*65 + 64*128)*4;    // 49408
    const int SM3  = (128*130 + 128*64)*4;  // 99328
    cudaFuncSetAttribute(k_enc12, cudaFuncAttributeMaxDynamicSharedMemorySize, SM12);
    cudaFuncSetAttribute(k_enc3,  cudaFuncAttributeMaxDynamicSharedMemorySize, SM3);

    k_init<<<256,1024>>>(points);

    int encoded = 0;
    for (int s=0; s<STEPS; s++){
        int N   = NPTS0 + NEWP*s;
        int seg = N - encoded;
        int e0  = encoded;
        int r   = s & 1;
        dim3 g1(seg/64, NB);
        k_enc12<<<g1,256,SM12>>>(e0, enc_w1, enc_b1, att_w1, enc_w2, enc_b2);
        dim3 g3(seg/128, 4, NB);
        k_enc3<<<g3,256,SM3>>>(enc_w3, enc_b3);
        encoded = N;
        dim3 ga((N+511)/512, NB);
        k_att<<<ga,256>>>(N, r, att_w1, att_b1, att_w2, att_b2);
        k_tailref<<<dim3(8,NB),1024>>>(N, r, s, lstm_wih, lstm_whh, lstm_bih, lstm_bhh,
                                       ref_w1, ref_b1, ref_w2, ref_b2);
    }
    k_cham2<<<dim3(23,6,16),128>>>(gt);
    k_chamsum<<<dim3(45,NB,4),256>>>(gt);
    k_final<<<1,32>>>((float*)d_out);
}